// round 2
// baseline (speedup 1.0000x reference)
#include <cuda_runtime.h>
#include <math.h>

#define NB 32
#define NL 1024
#define NC 512
#define LH 512   // L/2

// ---------------- scratch (device globals; no allocations) ----------------
__device__ float g_res[(size_t)2*NB*NC*NL];     // [2][B][C][L]
__device__ float g_cv [(size_t)NB*NC*86];       // conv out interleaved [B][C][2ne]
__device__ float g_x1 [(size_t)NB*NC*85];       // [B][C][m]
__device__ float g_xf [(size_t)NB*NC*169];      // [B][C][2m-1]
__device__ float g_xi [(size_t)NB*NC*85];
__device__ float g_xr [(size_t)NB*NC*85];
__device__ float g_yln[(size_t)NB*NC*85];
__device__ float g_y2 [(size_t)NB*NC*1032];     // [B][C][m*k]
__device__ float g_br [(size_t)NB*NL*2*NC];     // [B*L][2*C]
__device__ float g_mg [(size_t)NB*NL*NC];
__device__ float g_h1 [(size_t)NB*NL*4*NC];
__device__ float g_h2 [(size_t)NB*NL*NC];
__device__ float g_W2 [(size_t)NC*24*NC];
__device__ float g_Wm [(size_t)2*NC*NC];
__device__ float g_CM [85*169];
__device__ float g_CM2[85*85];

// ---------------- packed fp32x2 FMA (SASS FFMA2; ptxas won't emit from C++) --
__device__ __forceinline__ void ffma2(unsigned long long &d,
                                      unsigned long long a,
                                      unsigned long long b) {
    asm("fma.rn.f32x2 %0, %1, %2, %0;" : "+l"(d) : "l"(a), "l"(b));
}
union F2U { unsigned long long u; float2 f; };

// ---------------- series decomp ----------------
__global__ void decomp_kernel(const float* __restrict__ src, float* __restrict__ res) {
    __shared__ float s[64][33];
    int b = blockIdx.z;
    int c0 = blockIdx.y * 32;
    int l0 = blockIdx.x * 32;
    int tx = threadIdx.x, ty = threadIdx.y;
    for (int r = ty; r < 64; r += 32) {
        int l = l0 - 16 + r;
        l = l < 0 ? 0 : (l > NL - 1 ? NL - 1 : l);
        s[r][tx] = src[((size_t)b*NL + l)*NC + c0 + tx];
    }
    __syncthreads();
    int base = tx + 16;
    float s17 = 0.f;
    #pragma unroll
    for (int j = -8; j <= 8; j++) s17 += s[base + j][ty];
    float s33 = s17;
    #pragma unroll
    for (int j = 9; j <= 16; j++) s33 += s[base - j][ty] + s[base + j][ty];
    float v = s[base][ty];
    size_t o = ((size_t)(b*NC + c0 + ty))*NL + l0 + tx;
    res[o] = v - s17 / 17.0f;
    res[(size_t)NB*NC*NL + o] = v - s33 / 33.0f;
}

// ---------------- weight prep ----------------
__global__ void prep_trw_k(const float* __restrict__ tw, float* __restrict__ W2, int k) {
    int total = NC*NC*k;
    for (int idx = blockIdx.x*blockDim.x + threadIdx.x; idx < total; idx += gridDim.x*blockDim.x) {
        int cin = idx / (NC*k);
        int r   = idx - cin*(NC*k);
        W2[(size_t)r*NC + cin] = tw[idx];
    }
}
__global__ void prep_merge_k(const float* __restrict__ mwt, float* __restrict__ Wm) {
    int total = NC*NC*2;
    for (int idx = blockIdx.x*blockDim.x + threadIdx.x; idx < total; idx += gridDim.x*blockDim.x) {
        int o = idx / (NC*2);
        int rem = idx - o*NC*2;
        int c = rem >> 1, n = rem & 1;
        Wm[((size_t)n*NC + c)*NC + o] = mwt[idx];
    }
}
__global__ void build_cm_k(float* __restrict__ CM, float* __restrict__ CM2, int m, int N2) {
    const double TWO_PI = 6.283185307179586476925286766559;
    int t1 = m*N2, t2 = m*m;
    for (int idx = blockIdx.x*blockDim.x + threadIdx.x; idx < t1 + t2; idx += gridDim.x*blockDim.x) {
        if (idx < t1) {
            int t = idx / N2, f = idx - t*N2;
            CM[idx] = (float)cos(TWO_PI * (double)((long long)f*(t + m - 1)) / (double)N2);
        } else {
            int i2 = idx - t1;
            int f = i2 / m, t = i2 - f*m;
            CM2[i2] = (float)(cos(TWO_PI * (double)((long long)f*t) / (double)m) / (double)m);
        }
    }
}

// ---------------- x1: exp-gated interleave, drop last ----------------
__global__ void x1_kernel(const float* __restrict__ cv, float* __restrict__ x1, int m, int ne2) {
    size_t total = (size_t)NB*NC*m;
    for (size_t idx = (size_t)blockIdx.x*blockDim.x + threadIdx.x; idx < total;
         idx += (size_t)gridDim.x*blockDim.x) {
        int t = (int)(idx % m);
        size_t bc = idx / m;
        const float* c2 = cv + bc*ne2;
        x1[idx] = c2[t ^ 1] * expf(c2[t]);
    }
}

// ---------------- GEMM params ----------------
struct GemmP {
    const float* A; int lda;
    const float* Bp; int ldb; long long sBb;
    float* D; long long sDb; int ldd;
    const float* bias;
    int M, N, K;
    int npos;
    int pad, lhalf, inner;
    int kt, mklen;
};

// BMODE: 0 dense, 1 conv-im2col(even/odd), 2 iso-im2col     (KK: conv kernel size)
// BIASM: 0 none, 1 per-row, 2 per-col(q), 3 bias[row/kt]
// ACT:   0 none, 1 tanh, 2 relu
// SMODE: 0 normal, 1 transconv scatter
template<int BM, int BN, int BMODE, int KK, int BIASM, int ACT, int SMODE>
__global__ void __launch_bounds__(256)
gemm_k(GemmP p) {
    constexpr int BK = 16;
    constexpr int TM = BM/16, TN = BN/16;   // 16x16 threads
    constexpr int NJ = BN/16;               // B elements per thread per tile
    __shared__ float As2[BK][2*BM + 8];     // duplicated (a,a) pairs
    __shared__ float Bs[BK][BN];

    const int tid = threadIdx.x;
    const int tx = tid & 15, ty = tid >> 4;
    const int m0 = blockIdx.y * BM, n0 = blockIdx.x * BN;

    // hoisted per-j B column decomposition (gk-independent)
    const float* bptr[NJ];
    int  sb_j[NJ];           // mode1 base position
    bool nval[NJ];
    #pragma unroll
    for (int j = 0; j < NJ; j++) {
        int gn = n0 + tx + 16*j;
        nval[j] = gn < p.N;
        int gnc = nval[j] ? gn : 0;
        int b, q;
        if (BMODE == 0 && p.sBb == 0) { b = 0; q = gnc; }
        else { b = gnc / p.npos; q = gnc - b*p.npos; }
        if (BMODE == 0) {
            bptr[j] = p.Bp + b*p.sBb + q;
        } else if (BMODE == 1) {
            int o = q >> 1, pb = q & 1;
            sb_j[j] = o*KK - p.pad;
            bptr[j] = p.Bp + b*p.sBb + pb;
        } else {
            bptr[j] = p.Bp + b*p.sBb + q;
        }
    }
    // hoisted A row bases
    const int arow0 = tid >> 2;
    const int acol0 = (tid & 3) * 4;
    const float* aptr[BM/64];
    bool mval[BM/64];
    #pragma unroll
    for (int rep = 0; rep < BM/64; rep++) {
        int gm = m0 + arow0 + 64*rep;
        mval[rep] = gm < p.M;
        aptr[rep] = p.A + (long long)(mval[rep] ? gm : 0) * p.lda;
    }

    unsigned long long acc[TM][TN/2];
    #pragma unroll
    for (int i = 0; i < TM; i++)
        #pragma unroll
        for (int jp = 0; jp < TN/2; jp++) acc[i][jp] = 0ull;

    for (int k0 = 0; k0 < p.K; k0 += BK) {
        // --- A tile (duplicated pairs) ---
        #pragma unroll
        for (int rep = 0; rep < BM/64; rep++) {
            int r = arow0 + 64*rep;
            #pragma unroll
            for (int i = 0; i < 4; i++) {
                int gk = k0 + acol0 + i;
                float v = (mval[rep] && gk < p.K) ? aptr[rep][gk] : 0.f;
                As2[acol0 + i][2*r]     = v;
                As2[acol0 + i][2*r + 1] = v;
            }
        }
        // --- B tile ---
        {
            int gk = k0 + (tid >> 4);
            bool kval = gk < p.K;
            int cin = 0, t = 0;
            if (BMODE != 0) { cin = gk / KK; t = gk - cin*KK; }
            #pragma unroll
            for (int j = 0; j < NJ; j++) {
                float v = 0.f;
                if (kval && nval[j]) {
                    if (BMODE == 0) {
                        v = bptr[j][(long long)gk * p.ldb];
                    } else if (BMODE == 1) {
                        int s = sb_j[j] + t;
                        if (s >= 0 && s < p.lhalf)
                            v = bptr[j][(long long)cin*p.inner + 2*s];
                    } else {
                        v = bptr[j][(long long)cin*p.inner + t];
                    }
                }
                Bs[tid >> 4][tx + 16*j] = v;
            }
        }
        __syncthreads();
        #pragma unroll
        for (int kk = 0; kk < BK; kk++) {
            unsigned long long ap[TM];
            #pragma unroll
            for (int i = 0; i < TM; i++)
                ap[i] = *(const unsigned long long*)&As2[kk][2*(ty*TM + i)];
            unsigned long long bp[TN/2];
            #pragma unroll
            for (int u = 0; u < TN/4; u++) {
                ulonglong2 q2 = *(const ulonglong2*)&Bs[kk][tx*TN + 4*u];
                bp[2*u] = q2.x; bp[2*u + 1] = q2.y;
            }
            #pragma unroll
            for (int i = 0; i < TM; i++)
                #pragma unroll
                for (int jp = 0; jp < TN/2; jp++)
                    ffma2(acc[i][jp], ap[i], bp[jp]);
        }
        __syncthreads();
    }

    // --- epilogue ---
    #pragma unroll
    for (int i = 0; i < TM; i++) {
        int row = m0 + ty*TM + i;
        if (row >= p.M) continue;
        float brow = 0.f;
        if (BIASM == 1) brow = p.bias[row];
        else if (BIASM == 3) brow = p.bias[row / p.kt];
        int cout = 0, jj = 0;
        if (SMODE == 1) { cout = row / p.kt; jj = row - cout*p.kt; }
        #pragma unroll
        for (int jp = 0; jp < TN/2; jp++) {
            F2U u; u.u = acc[i][jp];
            float vals[2] = {u.f.x, u.f.y};
            #pragma unroll
            for (int e = 0; e < 2; e++) {
                int gn = n0 + tx*TN + 2*jp + e;
                if (gn >= p.N) continue;
                int b, q;
                if (SMODE == 0 && p.sDb == 0) { b = 0; q = gn; }
                else { b = gn / p.npos; q = gn - b*p.npos; }
                float v = vals[e] + brow;
                if (BIASM == 2) v += p.bias[q];
                if (ACT == 1) v = tanhf(v);
                else if (ACT == 2) v = fmaxf(v, 0.f);
                long long addr;
                if (SMODE == 0) addr = b*p.sDb + (long long)row*p.ldd + q;
                else addr = b*p.sDb + (long long)cout*p.mklen + (long long)q*p.kt + jj;
                p.D[addr] = v;
            }
        }
    }
}

// ---------------- block reduce + layer norms ----------
__device__ __forceinline__ float blk_sum(float v) {
    __shared__ float sb[8];
    #pragma unroll
    for (int o = 16; o; o >>= 1) v += __shfl_xor_sync(0xffffffffu, v, o);
    if ((threadIdx.x & 31) == 0) sb[threadIdx.x >> 5] = v;
    __syncthreads();
    float t = 0.f;
    #pragma unroll
    for (int i = 0; i < 8; i++) t += sb[i];
    __syncthreads();
    return t;
}

__global__ void ln1_kernel(const float* __restrict__ xr, const float* __restrict__ x1,
                           const float* __restrict__ g, const float* __restrict__ bt,
                           float* __restrict__ out, int m) {
    int row = blockIdx.x;
    int b = row / m, t = row - b*m;
    int tid = threadIdx.x;
    size_t base = (size_t)b*NC*m + t;
    float v0 = xr[base + (size_t)tid*m]       + x1[base + (size_t)tid*m];
    float v1 = xr[base + (size_t)(tid+256)*m] + x1[base + (size_t)(tid+256)*m];
    float mu = blk_sum(v0 + v1) * (1.f/NC);
    float d0 = v0 - mu, d1 = v1 - mu;
    float var = blk_sum(d0*d0 + d1*d1) * (1.f/NC);
    float inv = rsqrtf(var + 1e-5f);
    out[base + (size_t)tid*m]       = d0*inv*g[tid]     + bt[tid];
    out[base + (size_t)(tid+256)*m] = d1*inv*g[tid+256] + bt[tid+256];
}

__global__ void branch_out_kernel(const float* __restrict__ y2, const float* __restrict__ resn,
                                  const float* __restrict__ g, const float* __restrict__ bt,
                                  float* __restrict__ br, int mk, int nbr) {
    int row = blockIdx.x;
    int b = row >> 10, l = row & 1023;
    int li = (l * mk) >> 10;
    int tid = threadIdx.x;
    size_t yb = (size_t)b*NC*mk + li;
    size_t rb = (size_t)b*NC*NL + l;
    float v0 = y2[yb + (size_t)tid*mk]       + resn[rb + (size_t)tid*NL];
    float v1 = y2[yb + (size_t)(tid+256)*mk] + resn[rb + (size_t)(tid+256)*NL];
    float mu = blk_sum(v0 + v1) * (1.f/NC);
    float d0 = v0 - mu, d1 = v1 - mu;
    float var = blk_sum(d0*d0 + d1*d1) * (1.f/NC);
    float inv = rsqrtf(var + 1e-5f);
    float* o = br + (size_t)row*(2*NC) + nbr*NC;
    o[tid]     = d0*inv*g[tid]     + bt[tid];
    o[tid+256] = d1*inv*g[tid+256] + bt[tid+256];
}

__global__ void final_ln_kernel(const float* __restrict__ mg, const float* __restrict__ h2,
                                const float* __restrict__ g, const float* __restrict__ bt,
                                float* __restrict__ out) {
    int row = blockIdx.x;
    int tid = threadIdx.x;
    size_t base = (size_t)row*NC;
    float v0 = mg[base + tid]       + h2[base + tid];
    float v1 = mg[base + tid + 256] + h2[base + tid + 256];
    float mu = blk_sum(v0 + v1) * (1.f/NC);
    float d0 = v0 - mu, d1 = v1 - mu;
    float var = blk_sum(d0*d0 + d1*d1) * (1.f/NC);
    float inv = rsqrtf(var + 1e-5f);
    out[base + tid]       = d0*inv*g[tid]     + bt[tid];
    out[base + tid + 256] = d1*inv*g[tid+256] + bt[tid+256];
}

template<int BM, int BN>
static inline dim3 gg(int M, int N) { return dim3((N + BN - 1)/BN, (M + BM - 1)/BM, 1); }

extern "C" void kernel_launch(void* const* d_in, const int* in_sizes, int n_in,
                              void* d_out, int out_size) {
    (void)in_sizes; (void)n_in; (void)out_size;
    const float* src   = (const float*)d_in[0];
    const float* cw[2] = {(const float*)d_in[1],  (const float*)d_in[7]};
    const float* cb[2] = {(const float*)d_in[2],  (const float*)d_in[8]};
    const float* iw[2] = {(const float*)d_in[3],  (const float*)d_in[9]};
    const float* ib[2] = {(const float*)d_in[4],  (const float*)d_in[10]};
    const float* tw[2] = {(const float*)d_in[5],  (const float*)d_in[11]};
    const float* tb[2] = {(const float*)d_in[6],  (const float*)d_in[12]};
    const float* mw  = (const float*)d_in[13];
    const float* mb  = (const float*)d_in[14];
    const float* ng  = (const float*)d_in[15];
    const float* nb  = (const float*)d_in[16];
    const float* fw1 = (const float*)d_in[17];
    const float* fb1 = (const float*)d_in[18];
    const float* fw2 = (const float*)d_in[19];
    const float* fb2 = (const float*)d_in[20];
    const float* fng = (const float*)d_in[21];
    const float* fnb = (const float*)d_in[22];
    float* out = (float*)d_out;

    float *p_res,*p_cv,*p_x1,*p_xf,*p_xi,*p_xr,*p_yln,*p_y2,*p_br,*p_mg,*p_h1,*p_h2,*p_W2,*p_Wm,*p_CM,*p_CM2;
    cudaGetSymbolAddress((void**)&p_res, g_res);
    cudaGetSymbolAddress((void**)&p_cv,  g_cv);
    cudaGetSymbolAddress((void**)&p_x1,  g_x1);
    cudaGetSymbolAddress((void**)&p_xf,  g_xf);
    cudaGetSymbolAddress((void**)&p_xi,  g_xi);
    cudaGetSymbolAddress((void**)&p_xr,  g_xr);
    cudaGetSymbolAddress((void**)&p_yln, g_yln);
    cudaGetSymbolAddress((void**)&p_y2,  g_y2);
    cudaGetSymbolAddress((void**)&p_br,  g_br);
    cudaGetSymbolAddress((void**)&p_mg,  g_mg);
    cudaGetSymbolAddress((void**)&p_h1,  g_h1);
    cudaGetSymbolAddress((void**)&p_h2,  g_h2);
    cudaGetSymbolAddress((void**)&p_W2,  g_W2);
    cudaGetSymbolAddress((void**)&p_Wm,  g_Wm);
    cudaGetSymbolAddress((void**)&p_CM,  g_CM);
    cudaGetSymbolAddress((void**)&p_CM2, g_CM2);

    decomp_kernel<<<dim3(NL/32, NC/32, NB), dim3(32, 32)>>>(src, p_res);
    prep_merge_k<<<1024, 256>>>(mw, p_Wm);

    const int Kk[2] = {12, 24}, PD[2] = {6, 12}, NE[2] = {43, 22},
              MM[2] = {85, 43}, N2_[2] = {169, 85}, MKl[2] = {1020, 1032};

    for (int n = 0; n < 2; n++) {
        int k = Kk[n], pad = PD[n], ne = NE[n], m = MM[n], N2 = N2_[n], mk = MKl[n];
        int ne2 = 2*ne;
        build_cm_k<<<256, 256>>>(p_CM, p_CM2, m, N2);
        prep_trw_k<<<4096, 256>>>(tw[n], p_W2, k);

        { // strided conv (even+odd interleaved), tanh
            GemmP p{};
            p.A = cw[n]; p.lda = NC*k;
            p.Bp = p_res + (size_t)n*NB*NC*NL; p.sBb = (long long)NC*NL;
            p.pad = pad; p.lhalf = LH; p.inner = NL;
            p.D = p_cv; p.sDb = (long long)NC*ne2; p.ldd = ne2;
            p.bias = cb[n];
            p.M = NC; p.N = NB*ne2; p.K = NC*k; p.npos = ne2;
            if (n == 0) gemm_k<64,128,1,12,1,1,0><<<gg<64,128>(p.M,p.N), 256>>>(p);
            else        gemm_k<64,64, 1,24,1,1,0><<<gg<64,64 >(p.M,p.N), 256>>>(p);
        }
        x1_kernel<<<1024, 256>>>(p_cv, p_x1, m, ne2);
        { // real-DFT
            GemmP p{};
            p.A = p_x1; p.lda = m;
            p.Bp = p_CM; p.ldb = N2; p.sBb = 0;
            p.D = p_xf; p.sDb = 0; p.ldd = N2;
            p.M = NB*NC; p.N = N2; p.K = m; p.npos = N2;
            gemm_k<128,64,0,0,0,0,0><<<gg<128,64>(p.M,p.N), 256>>>(p);
        }
        { // isometric conv (valid), tanh
            GemmP p{};
            p.A = iw[n]; p.lda = NC*m;
            p.Bp = p_xf; p.sBb = (long long)NC*N2; p.inner = N2;
            p.D = p_xi; p.sDb = (long long)NC*m; p.ldd = m;
            p.bias = ib[n];
            p.M = NC; p.N = NB*m; p.K = NC*m; p.npos = m;
            if (n == 0) gemm_k<64,128,2,85,1,1,0><<<gg<64,128>(p.M,p.N), 256>>>(p);
            else        gemm_k<64,64, 2,43,1,1,0><<<gg<64,64 >(p.M,p.N), 256>>>(p);
        }
        { // real-IDFT
            GemmP p{};
            p.A = p_xi; p.lda = m;
            p.Bp = p_CM2; p.ldb = m; p.sBb = 0;
            p.D = p_xr; p.sDb = 0; p.ldd = m;
            p.M = NB*NC; p.N = m; p.K = m; p.npos = m;
            gemm_k<128,64,0,0,0,0,0><<<gg<128,64>(p.M,p.N), 256>>>(p);
        }
        ln1_kernel<<<NB*m, 256>>>(p_xr, p_x1, ng, nb, p_yln, m);
        { // conv-transpose (stride==kernel), tanh, scatter store
            GemmP p{};
            p.A = p_W2; p.lda = NC;
            p.Bp = p_yln; p.ldb = m; p.sBb = (long long)NC*m;
            p.D = p_y2; p.sDb = (long long)NC*mk; p.kt = k; p.mklen = mk;
            p.bias = tb[n];
            p.M = NC*k; p.N = NB*m; p.K = NC; p.npos = m;
            gemm_k<128,128,0,0,3,1,1><<<gg<128,128>(p.M,p.N), 256>>>(p);
        }
        branch_out_kernel<<<NB*NL, 256>>>(p_y2, p_res + (size_t)n*NB*NC*NL, ng, nb, p_br, mk, n);
    }
    { // merge
        GemmP p{};
        p.A = p_br; p.lda = 2*NC;
        p.Bp = p_Wm; p.ldb = NC; p.sBb = 0;
        p.D = p_mg; p.sDb = 0; p.ldd = NC;
        p.bias = mb;
        p.M = NB*NL; p.N = NC; p.K = 2*NC; p.npos = NC;
        gemm_k<128,128,0,0,2,0,0><<<gg<128,128>(p.M,p.N), 256>>>(p);
    }
    { // FFN layer 1 (relu)
        GemmP p{};
        p.A = p_mg; p.lda = NC;
        p.Bp = fw1; p.ldb = 4*NC; p.sBb = 0;
        p.D = p_h1; p.sDb = 0; p.ldd = 4*NC;
        p.bias = fb1;
        p.M = NB*NL; p.N = 4*NC; p.K = NC; p.npos = 4*NC;
        gemm_k<128,128,0,0,2,2,0><<<gg<128,128>(p.M,p.N), 256>>>(p);
    }
    { // FFN layer 2
        GemmP p{};
        p.A = p_h1; p.lda = 4*NC;
        p.Bp = fw2; p.ldb = NC; p.sBb = 0;
        p.D = p_h2; p.sDb = 0; p.ldd = NC;
        p.bias = fb2;
        p.M = NB*NL; p.N = NC; p.K = 4*NC; p.npos = NC;
        gemm_k<128,128,0,0,2,0,0><<<gg<128,128>(p.M,p.N), 256>>>(p);
    }
    final_ln_kernel<<<NB*NL, 256>>>(p_mg, p_h2, fng, fnb, out);
}

// round 3
// speedup vs baseline: 1.4478x; 1.4478x over previous
#include <cuda_runtime.h>
#include <math.h>
#include <stdint.h>

#define NB 32
#define NL 1024
#define NC 512
#define LH 512   // L/2

// ---------------- scratch (device globals; no allocations) ----------------
__device__ float g_res[(size_t)2*NB*NC*NL];     // [2][B][C][L]
__device__ float g_cv [(size_t)NB*NC*86];       // conv out interleaved [B][C][2ne]
__device__ float g_x1 [(size_t)NB*NC*85];       // [B][C][m]
__device__ float g_xf [(size_t)NB*NC*169];      // [B][C][2m-1]
__device__ float g_xi [(size_t)NB*NC*85];
__device__ float g_xr [(size_t)NB*NC*85];
__device__ float g_yln[(size_t)NB*NC*85];
__device__ float g_y2 [(size_t)NB*NC*1032];     // [B][C][m*k]
__device__ float g_br [(size_t)NB*NL*2*NC];     // [B*L][2*C]
__device__ float g_mg [(size_t)NB*NL*NC];
__device__ float g_h1 [(size_t)NB*NL*4*NC];
__device__ float g_h2 [(size_t)NB*NL*NC];
__device__ float g_W2 [(size_t)NC*24*NC];
__device__ float g_Wm [(size_t)2*NC*NC];
__device__ float g_CM [85*169];
__device__ float g_CM2[85*85];

// ---------------- series decomp ----------------
__global__ void decomp_kernel(const float* __restrict__ src, float* __restrict__ res) {
    __shared__ float s[64][33];
    int b = blockIdx.z;
    int c0 = blockIdx.y * 32;
    int l0 = blockIdx.x * 32;
    int tx = threadIdx.x, ty = threadIdx.y;
    for (int r = ty; r < 64; r += 32) {
        int l = l0 - 16 + r;
        l = l < 0 ? 0 : (l > NL - 1 ? NL - 1 : l);
        s[r][tx] = src[((size_t)b*NL + l)*NC + c0 + tx];
    }
    __syncthreads();
    int base = tx + 16;
    float s17 = 0.f;
    #pragma unroll
    for (int j = -8; j <= 8; j++) s17 += s[base + j][ty];
    float s33 = s17;
    #pragma unroll
    for (int j = 9; j <= 16; j++) s33 += s[base - j][ty] + s[base + j][ty];
    float v = s[base][ty];
    size_t o = ((size_t)(b*NC + c0 + ty))*NL + l0 + tx;
    res[o] = v - s17 / 17.0f;
    res[(size_t)NB*NC*NL + o] = v - s33 / 33.0f;
}

// ---------------- weight prep ----------------
__global__ void prep_trw_k(const float* __restrict__ tw, float* __restrict__ W2, int k) {
    int total = NC*NC*k;
    for (int idx = blockIdx.x*blockDim.x + threadIdx.x; idx < total; idx += gridDim.x*blockDim.x) {
        int cin = idx / (NC*k);
        int r   = idx - cin*(NC*k);
        W2[(size_t)r*NC + cin] = tw[idx];
    }
}
__global__ void prep_merge_k(const float* __restrict__ mwt, float* __restrict__ Wm) {
    int total = NC*NC*2;
    for (int idx = blockIdx.x*blockDim.x + threadIdx.x; idx < total; idx += gridDim.x*blockDim.x) {
        int o = idx / (NC*2);
        int rem = idx - o*NC*2;
        int c = rem >> 1, n = rem & 1;
        Wm[((size_t)n*NC + c)*NC + o] = mwt[idx];
    }
}
__global__ void build_cm_k(float* __restrict__ CM, float* __restrict__ CM2, int m, int N2) {
    const double TWO_PI = 6.283185307179586476925286766559;
    int t1 = m*N2, t2 = m*m;
    for (int idx = blockIdx.x*blockDim.x + threadIdx.x; idx < t1 + t2; idx += gridDim.x*blockDim.x) {
        if (idx < t1) {
            int t = idx / N2, f = idx - t*N2;
            CM[idx] = (float)cos(TWO_PI * (double)((long long)f*(t + m - 1)) / (double)N2);
        } else {
            int i2 = idx - t1;
            int f = i2 / m, t = i2 - f*m;
            CM2[i2] = (float)(cos(TWO_PI * (double)((long long)f*t) / (double)m) / (double)m);
        }
    }
}

// ---------------- x1: exp-gated interleave, drop last ----------------
__global__ void x1_kernel(const float* __restrict__ cv, float* __restrict__ x1, int m, int ne2) {
    size_t total = (size_t)NB*NC*m;
    for (size_t idx = (size_t)blockIdx.x*blockDim.x + threadIdx.x; idx < total;
         idx += (size_t)gridDim.x*blockDim.x) {
        int t = (int)(idx % m);
        size_t bc = idx / m;
        const float* c2 = cv + bc*ne2;
        x1[idx] = c2[t ^ 1] * expf(c2[t]);
    }
}

// ---------------- GEMM params ----------------
struct GemmP {
    const float* A; int lda;
    const float* Bp; int ldb; long long sBb;
    float* D; long long sDb; int ldd;
    const float* bias;
    int M, N, K;
    int npos;
    int pad, lhalf, inner;
    int kt, mklen;
};

__device__ __forceinline__ uint32_t f2tf32(float v) {
    uint32_t u;
    asm("cvt.rna.tf32.f32 %0, %1;" : "=r"(u) : "f"(v));
    return u;
}

__device__ __forceinline__ void mma_tf32(float c[4], const uint32_t a[4], const uint32_t b[2]) {
    asm("mma.sync.aligned.m16n8k8.row.col.f32.tf32.tf32.f32 "
        "{%0,%1,%2,%3},{%4,%5,%6,%7},{%8,%9},{%0,%1,%2,%3};"
        : "+f"(c[0]), "+f"(c[1]), "+f"(c[2]), "+f"(c[3])
        : "r"(a[0]), "r"(a[1]), "r"(a[2]), "r"(a[3]), "r"(b[0]), "r"(b[1]));
}

// BMODE: 0 dense, 1 conv-im2col(even/odd), 2 iso-im2col     (KK: conv kernel size)
// BIASM: 0 none, 1 per-row, 2 per-col(q), 3 bias[row/kt]
// ACT:   0 none, 1 tanh, 2 relu
// SMODE: 0 normal, 1 transconv scatter
// Requires: M % BM == 0.
template<int BM, int BN, int BMODE, int KK, int BIASM, int ACT, int SMODE>
__global__ void __launch_bounds__(256)
gemm_k(GemmP p) {
    constexpr int BK = 32;
    constexpr int WR = BM/32;       // warp rows (BM=64 -> 2, BM=128 -> 4)
    constexpr int WC = 8/WR;        // warp cols
    constexpr int WN = BN/WC;       // per-warp N extent
    constexpr int NF = WN/8;        // n fragments per warp
    __shared__ float As[BK][BM + 8];
    __shared__ float Bs[BK][BN + 8];

    const int tid = threadIdx.x, lane = tid & 31, warp = tid >> 5;
    const int wr = warp % WR, wc = warp / WR;
    const int m0 = blockIdx.y * BM, n0 = blockIdx.x * BN;

    const int fl = tid & 31;        // fill lane (spans m or n)
    const int fk = (tid >> 5) * 4;  // fill k base

    float acc[2][NF][4];
    #pragma unroll
    for (int mi = 0; mi < 2; mi++)
        #pragma unroll
        for (int ni = 0; ni < NF; ni++)
            #pragma unroll
            for (int e = 0; e < 4; e++) acc[mi][ni][e] = 0.f;

    for (int k0 = 0; k0 < p.K; k0 += BK) {
        // ---- A fill: As[k][m] ----
        #pragma unroll
        for (int rep = 0; rep < BM/32; rep++) {
            int m = fl + 32*rep;
            const float* arow = p.A + (long long)(m0 + m) * p.lda;
            #pragma unroll
            for (int i = 0; i < 4; i++) {
                int gk = k0 + fk + i;
                float v = (gk < p.K) ? arow[gk] : 0.f;
                As[fk + i][m] = __uint_as_float(f2tf32(v));
            }
        }
        // ---- B fill: Bs[k][n] ----
        #pragma unroll
        for (int rep = 0; rep < BN/32; rep++) {
            int nn = fl + 32*rep;
            int gn = n0 + nn;
            bool nv = gn < p.N;
            int b = 0, q = gn;
            if (!(BMODE == 0 && p.sBb == 0)) {
                int gnc = nv ? gn : 0;
                b = gnc / p.npos; q = gnc - b*p.npos;
            }
            const float* bbase;
            int sb = 0;
            if (BMODE == 0) bbase = p.Bp + b*p.sBb + q;
            else if (BMODE == 1) { int o = q >> 1; int pb = q & 1; sb = o*KK - p.pad; bbase = p.Bp + b*p.sBb + pb; }
            else bbase = p.Bp + b*p.sBb + q;
            #pragma unroll
            for (int i = 0; i < 4; i++) {
                int gk = k0 + fk + i;
                float v = 0.f;
                if (nv && gk < p.K) {
                    if (BMODE == 0) {
                        v = bbase[(long long)gk * p.ldb];
                    } else {
                        int cin = gk / KK, t = gk - cin*KK;
                        if (BMODE == 1) {
                            int s = sb + t;
                            if (s >= 0 && s < p.lhalf) v = bbase[(long long)cin*p.inner + 2*s];
                        } else {
                            v = bbase[(long long)cin*p.inner + t];
                        }
                    }
                }
                Bs[fk + i][nn] = __uint_as_float(f2tf32(v));
            }
        }
        __syncthreads();
        // ---- compute ----
        const int r = lane >> 2, c = lane & 3;
        #pragma unroll
        for (int kc = 0; kc < 4; kc++) {
            int kb = kc * 8;
            uint32_t af[2][4];
            #pragma unroll
            for (int mi = 0; mi < 2; mi++) {
                int mb = wr*32 + mi*16;
                af[mi][0] = __float_as_uint(As[kb + c    ][mb + r    ]);
                af[mi][1] = __float_as_uint(As[kb + c    ][mb + r + 8]);
                af[mi][2] = __float_as_uint(As[kb + c + 4][mb + r    ]);
                af[mi][3] = __float_as_uint(As[kb + c + 4][mb + r + 8]);
            }
            uint32_t bf[NF][2];
            #pragma unroll
            for (int ni = 0; ni < NF; ni++) {
                int nb = wc*WN + ni*8 + r;
                bf[ni][0] = __float_as_uint(Bs[kb + c    ][nb]);
                bf[ni][1] = __float_as_uint(Bs[kb + c + 4][nb]);
            }
            #pragma unroll
            for (int mi = 0; mi < 2; mi++)
                #pragma unroll
                for (int ni = 0; ni < NF; ni++)
                    mma_tf32(acc[mi][ni], af[mi], bf[ni]);
        }
        __syncthreads();
    }

    // ---- epilogue ----
    #pragma unroll
    for (int mi = 0; mi < 2; mi++) {
        #pragma unroll
        for (int half = 0; half < 2; half++) {
            int row = m0 + wr*32 + mi*16 + (lane >> 2) + half*8;
            if (row >= p.M) continue;
            float brow = 0.f;
            if (BIASM == 1) brow = p.bias[row];
            else if (BIASM == 3) brow = p.bias[row / p.kt];
            int cout = 0, jj = 0;
            if (SMODE == 1) { cout = row / p.kt; jj = row - cout*p.kt; }
            #pragma unroll
            for (int ni = 0; ni < NF; ni++) {
                #pragma unroll
                for (int e = 0; e < 2; e++) {
                    int gn = n0 + wc*WN + ni*8 + (lane & 3)*2 + e;
                    if (gn >= p.N) continue;
                    int b, q;
                    if (SMODE == 0 && p.sDb == 0) { b = 0; q = gn; }
                    else { b = gn / p.npos; q = gn - b*p.npos; }
                    float v = acc[mi][ni][half*2 + e] + brow;
                    if (BIASM == 2) v += p.bias[q];
                    if (ACT == 1) v = tanhf(v);
                    else if (ACT == 2) v = fmaxf(v, 0.f);
                    long long addr;
                    if (SMODE == 0) addr = b*p.sDb + (long long)row*p.ldd + q;
                    else addr = b*p.sDb + (long long)cout*p.mklen + (long long)q*p.kt + jj;
                    p.D[addr] = v;
                }
            }
        }
    }
}

// ---------------- block reduce + layer norms ----------
__device__ __forceinline__ float blk_sum(float v) {
    __shared__ float sb[8];
    #pragma unroll
    for (int o = 16; o; o >>= 1) v += __shfl_xor_sync(0xffffffffu, v, o);
    if ((threadIdx.x & 31) == 0) sb[threadIdx.x >> 5] = v;
    __syncthreads();
    float t = 0.f;
    #pragma unroll
    for (int i = 0; i < 8; i++) t += sb[i];
    __syncthreads();
    return t;
}

__global__ void ln1_kernel(const float* __restrict__ xr, const float* __restrict__ x1,
                           const float* __restrict__ g, const float* __restrict__ bt,
                           float* __restrict__ out, int m) {
    int row = blockIdx.x;
    int b = row / m, t = row - b*m;
    int tid = threadIdx.x;
    size_t base = (size_t)b*NC*m + t;
    float v0 = xr[base + (size_t)tid*m]       + x1[base + (size_t)tid*m];
    float v1 = xr[base + (size_t)(tid+256)*m] + x1[base + (size_t)(tid+256)*m];
    float mu = blk_sum(v0 + v1) * (1.f/NC);
    float d0 = v0 - mu, d1 = v1 - mu;
    float var = blk_sum(d0*d0 + d1*d1) * (1.f/NC);
    float inv = rsqrtf(var + 1e-5f);
    out[base + (size_t)tid*m]       = d0*inv*g[tid]     + bt[tid];
    out[base + (size_t)(tid+256)*m] = d1*inv*g[tid+256] + bt[tid+256];
}

__global__ void branch_out_kernel(const float* __restrict__ y2, const float* __restrict__ resn,
                                  const float* __restrict__ g, const float* __restrict__ bt,
                                  float* __restrict__ br, int mk, int nbr) {
    int row = blockIdx.x;
    int b = row >> 10, l = row & 1023;
    int li = (l * mk) >> 10;
    int tid = threadIdx.x;
    size_t yb = (size_t)b*NC*mk + li;
    size_t rb = (size_t)b*NC*NL + l;
    float v0 = y2[yb + (size_t)tid*mk]       + resn[rb + (size_t)tid*NL];
    float v1 = y2[yb + (size_t)(tid+256)*mk] + resn[rb + (size_t)(tid+256)*NL];
    float mu = blk_sum(v0 + v1) * (1.f/NC);
    float d0 = v0 - mu, d1 = v1 - mu;
    float var = blk_sum(d0*d0 + d1*d1) * (1.f/NC);
    float inv = rsqrtf(var + 1e-5f);
    float* o = br + (size_t)row*(2*NC) + nbr*NC;
    o[tid]     = d0*inv*g[tid]     + bt[tid];
    o[tid+256] = d1*inv*g[tid+256] + bt[tid+256];
}

__global__ void final_ln_kernel(const float* __restrict__ mg, const float* __restrict__ h2,
                                const float* __restrict__ g, const float* __restrict__ bt,
                                float* __restrict__ out) {
    int row = blockIdx.x;
    int tid = threadIdx.x;
    size_t base = (size_t)row*NC;
    float v0 = mg[base + tid]       + h2[base + tid];
    float v1 = mg[base + tid + 256] + h2[base + tid + 256];
    float mu = blk_sum(v0 + v1) * (1.f/NC);
    float d0 = v0 - mu, d1 = v1 - mu;
    float var = blk_sum(d0*d0 + d1*d1) * (1.f/NC);
    float inv = rsqrtf(var + 1e-5f);
    out[base + tid]       = d0*inv*g[tid]     + bt[tid];
    out[base + tid + 256] = d1*inv*g[tid+256] + bt[tid+256];
}

template<int BM, int BN>
static inline dim3 gg(int M, int N) { return dim3((N + BN - 1)/BN, (M + BM - 1)/BM, 1); }

extern "C" void kernel_launch(void* const* d_in, const int* in_sizes, int n_in,
                              void* d_out, int out_size) {
    (void)in_sizes; (void)n_in; (void)out_size;
    const float* src   = (const float*)d_in[0];
    const float* cw[2] = {(const float*)d_in[1],  (const float*)d_in[7]};
    const float* cb[2] = {(const float*)d_in[2],  (const float*)d_in[8]};
    const float* iw[2] = {(const float*)d_in[3],  (const float*)d_in[9]};
    const float* ib[2] = {(const float*)d_in[4],  (const float*)d_in[10]};
    const float* tw[2] = {(const float*)d_in[5],  (const float*)d_in[11]};
    const float* tb[2] = {(const float*)d_in[6],  (const float*)d_in[12]};
    const float* mw  = (const float*)d_in[13];
    const float* mb  = (const float*)d_in[14];
    const float* ng  = (const float*)d_in[15];
    const float* nb  = (const float*)d_in[16];
    const float* fw1 = (const float*)d_in[17];
    const float* fb1 = (const float*)d_in[18];
    const float* fw2 = (const float*)d_in[19];
    const float* fb2 = (const float*)d_in[20];
    const float* fng = (const float*)d_in[21];
    const float* fnb = (const float*)d_in[22];
    float* out = (float*)d_out;

    float *p_res,*p_cv,*p_x1,*p_xf,*p_xi,*p_xr,*p_yln,*p_y2,*p_br,*p_mg,*p_h1,*p_h2,*p_W2,*p_Wm,*p_CM,*p_CM2;
    cudaGetSymbolAddress((void**)&p_res, g_res);
    cudaGetSymbolAddress((void**)&p_cv,  g_cv);
    cudaGetSymbolAddress((void**)&p_x1,  g_x1);
    cudaGetSymbolAddress((void**)&p_xf,  g_xf);
    cudaGetSymbolAddress((void**)&p_xi,  g_xi);
    cudaGetSymbolAddress((void**)&p_xr,  g_xr);
    cudaGetSymbolAddress((void**)&p_yln, g_yln);
    cudaGetSymbolAddress((void**)&p_y2,  g_y2);
    cudaGetSymbolAddress((void**)&p_br,  g_br);
    cudaGetSymbolAddress((void**)&p_mg,  g_mg);
    cudaGetSymbolAddress((void**)&p_h1,  g_h1);
    cudaGetSymbolAddress((void**)&p_h2,  g_h2);
    cudaGetSymbolAddress((void**)&p_W2,  g_W2);
    cudaGetSymbolAddress((void**)&p_Wm,  g_Wm);
    cudaGetSymbolAddress((void**)&p_CM,  g_CM);
    cudaGetSymbolAddress((void**)&p_CM2, g_CM2);

    decomp_kernel<<<dim3(NL/32, NC/32, NB), dim3(32, 32)>>>(src, p_res);
    prep_merge_k<<<1024, 256>>>(mw, p_Wm);

    const int Kk[2] = {12, 24}, PD[2] = {6, 12}, NE[2] = {43, 22},
              MM[2] = {85, 43}, N2_[2] = {169, 85}, MKl[2] = {1020, 1032};

    for (int n = 0; n < 2; n++) {
        int k = Kk[n], pad = PD[n], ne = NE[n], m = MM[n], N2 = N2_[n], mk = MKl[n];
        int ne2 = 2*ne;
        build_cm_k<<<256, 256>>>(p_CM, p_CM2, m, N2);
        prep_trw_k<<<4096, 256>>>(tw[n], p_W2, k);

        { // strided conv (even+odd interleaved), tanh
            GemmP p{};
            p.A = cw[n]; p.lda = NC*k;
            p.Bp = p_res + (size_t)n*NB*NC*NL; p.sBb = (long long)NC*NL;
            p.pad = pad; p.lhalf = LH; p.inner = NL;
            p.D = p_cv; p.sDb = (long long)NC*ne2; p.ldd = ne2;
            p.bias = cb[n];
            p.M = NC; p.N = NB*ne2; p.K = NC*k; p.npos = ne2;
            if (n == 0) gemm_k<64,128,1,12,1,1,0><<<gg<64,128>(p.M,p.N), 256>>>(p);
            else        gemm_k<64,128,1,24,1,1,0><<<gg<64,128>(p.M,p.N), 256>>>(p);
        }
        x1_kernel<<<1024, 256>>>(p_cv, p_x1, m, ne2);
        { // real-DFT
            GemmP p{};
            p.A = p_x1; p.lda = m;
            p.Bp = p_CM; p.ldb = N2; p.sBb = 0;
            p.D = p_xf; p.sDb = 0; p.ldd = N2;
            p.M = NB*NC; p.N = N2; p.K = m; p.npos = N2;
            gemm_k<128,64,0,0,0,0,0><<<gg<128,64>(p.M,p.N), 256>>>(p);
        }
        { // isometric conv (valid), tanh
            GemmP p{};
            p.A = iw[n]; p.lda = NC*m;
            p.Bp = p_xf; p.sBb = (long long)NC*N2; p.inner = N2;
            p.D = p_xi; p.sDb = (long long)NC*m; p.ldd = m;
            p.bias = ib[n];
            p.M = NC; p.N = NB*m; p.K = NC*m; p.npos = m;
            if (n == 0) gemm_k<64,128,2,85,1,1,0><<<gg<64,128>(p.M,p.N), 256>>>(p);
            else        gemm_k<64,128,2,43,1,1,0><<<gg<64,128>(p.M,p.N), 256>>>(p);
        }
        { // real-IDFT
            GemmP p{};
            p.A = p_xi; p.lda = m;
            p.Bp = p_CM2; p.ldb = m; p.sBb = 0;
            p.D = p_xr; p.sDb = 0; p.ldd = m;
            p.M = NB*NC; p.N = m; p.K = m; p.npos = m;
            gemm_k<128,64,0,0,0,0,0><<<gg<128,64>(p.M,p.N), 256>>>(p);
        }
        ln1_kernel<<<NB*m, 256>>>(p_xr, p_x1, ng, nb, p_yln, m);
        { // conv-transpose (stride==kernel), tanh, scatter store
            GemmP p{};
            p.A = p_W2; p.lda = NC;
            p.Bp = p_yln; p.ldb = m; p.sBb = (long long)NC*m;
            p.D = p_y2; p.sDb = (long long)NC*mk; p.kt = k; p.mklen = mk;
            p.bias = tb[n];
            p.M = NC*k; p.N = NB*m; p.K = NC; p.npos = m;
            gemm_k<128,128,0,0,3,1,1><<<gg<128,128>(p.M,p.N), 256>>>(p);
        }
        branch_out_kernel<<<NB*NL, 256>>>(p_y2, p_res + (size_t)n*NB*NC*NL, ng, nb, p_br, mk, n);
    }
    { // merge
        GemmP p{};
        p.A = p_br; p.lda = 2*NC;
        p.Bp = p_Wm; p.ldb = NC; p.sBb = 0;
        p.D = p_mg; p.sDb = 0; p.ldd = NC;
        p.bias = mb;
        p.M = NB*NL; p.N = NC; p.K = 2*NC; p.npos = NC;
        gemm_k<128,128,0,0,2,0,0><<<gg<128,128>(p.M,p.N), 256>>>(p);
    }
    { // FFN layer 1 (relu)
        GemmP p{};
        p.A = p_mg; p.lda = NC;
        p.Bp = fw1; p.ldb = 4*NC; p.sBb = 0;
        p.D = p_h1; p.sDb = 0; p.ldd = 4*NC;
        p.bias = fb1;
        p.M = NB*NL; p.N = 4*NC; p.K = NC; p.npos = 4*NC;
        gemm_k<128,128,0,0,2,2,0><<<gg<128,128>(p.M,p.N), 256>>>(p);
    }
    { // FFN layer 2
        GemmP p{};
        p.A = p_h1; p.lda = 4*NC;
        p.Bp = fw2; p.ldb = NC; p.sBb = 0;
        p.D = p_h2; p.sDb = 0; p.ldd = NC;
        p.bias = fb2;
        p.M = NB*NL; p.N = NC; p.K = 4*NC; p.npos = NC;
        gemm_k<128,128,0,0,2,0,0><<<gg<128,128>(p.M,p.N), 256>>>(p);
    }
    final_ln_kernel<<<NB*NL, 256>>>(p_mg, p_h2, fng, fnb, out);
}

// round 5
// speedup vs baseline: 2.0843x; 1.4397x over previous
#include <cuda_runtime.h>
#include <math.h>
#include <stdint.h>

#define NB 32
#define NL 1024
#define NC 512
#define LH 512   // L/2

// ---------------- scratch (device globals; no allocations) ----------------
__device__ float g_res[(size_t)2*NB*NC*NL];     // [2][B][C][L]
__device__ float g_cv [(size_t)NB*NC*86];       // conv out interleaved [B][C][2ne]
__device__ float g_x1 [(size_t)NB*NC*85];       // [B][C][m]
__device__ float g_xf [(size_t)NB*NC*169];      // [B][C][2m-1]
__device__ float g_xi [(size_t)NB*NC*85];
__device__ float g_xr [(size_t)NB*NC*85];
__device__ float g_yln[(size_t)NB*NC*85];
__device__ float g_y2 [(size_t)NB*NC*1032];     // [B][C][m*k]
__device__ float g_br [(size_t)NB*NL*2*NC];     // [B*L][2*C]
__device__ float g_mg [(size_t)NB*NL*NC];
__device__ float g_h1 [(size_t)NB*NL*4*NC];
__device__ float g_h2 [(size_t)NB*NL*NC];
__device__ float g_W2a[(size_t)NC*12*NC];
__device__ float g_W2b[(size_t)NC*24*NC];
__device__ float g_Wm [(size_t)2*NC*NC];
__device__ float g_CM0 [85*169];
__device__ float g_CM20[85*85];
__device__ float g_CM1 [43*85];
__device__ float g_CM21[43*43];

// ---------------- series decomp ----------------
__global__ void decomp_kernel(const float* __restrict__ src, float* __restrict__ res) {
    __shared__ float s[64][33];
    int b = blockIdx.z;
    int c0 = blockIdx.y * 32;
    int l0 = blockIdx.x * 32;
    int tx = threadIdx.x, ty = threadIdx.y;
    for (int r = ty; r < 64; r += 32) {
        int l = l0 - 16 + r;
        l = l < 0 ? 0 : (l > NL - 1 ? NL - 1 : l);
        s[r][tx] = src[((size_t)b*NL + l)*NC + c0 + tx];
    }
    __syncthreads();
    int base = tx + 16;
    float s17 = 0.f;
    #pragma unroll
    for (int j = -8; j <= 8; j++) s17 += s[base + j][ty];
    float s33 = s17;
    #pragma unroll
    for (int j = 9; j <= 16; j++) s33 += s[base - j][ty] + s[base + j][ty];
    float v = s[base][ty];
    size_t o = ((size_t)(b*NC + c0 + ty))*NL + l0 + tx;
    res[o] = v - s17 / 17.0f;
    res[(size_t)NB*NC*NL + o] = v - s33 / 33.0f;
}

// ---------------- weight prep ----------------
__global__ void prep_trw_k(const float* __restrict__ tw, float* __restrict__ W2, int k) {
    int total = NC*NC*k;
    for (int idx = blockIdx.x*blockDim.x + threadIdx.x; idx < total; idx += gridDim.x*blockDim.x) {
        int cin = idx / (NC*k);
        int r   = idx - cin*(NC*k);
        W2[(size_t)r*NC + cin] = tw[idx];
    }
}
__global__ void prep_merge_k(const float* __restrict__ mwt, float* __restrict__ Wm) {
    int total = NC*NC*2;
    for (int idx = blockIdx.x*blockDim.x + threadIdx.x; idx < total; idx += gridDim.x*blockDim.x) {
        int o = idx / (NC*2);
        int rem = idx - o*NC*2;
        int c = rem >> 1, n = rem & 1;
        Wm[((size_t)n*NC + c)*NC + o] = mwt[idx];
    }
}
__global__ void build_cm_all(float* __restrict__ CM0, float* __restrict__ CM20,
                             float* __restrict__ CM1, float* __restrict__ CM21) {
    const double TWO_PI = 6.283185307179586476925286766559;
    const int t0 = 85*169, t1 = 85*85, t2 = 43*85, t3 = 43*43;
    int total = t0 + t1 + t2 + t3;
    for (int idx = blockIdx.x*blockDim.x + threadIdx.x; idx < total; idx += gridDim.x*blockDim.x) {
        if (idx < t0) {
            int t = idx / 169, f = idx - t*169;
            CM0[idx] = (float)cos(TWO_PI * (double)((long long)f*(t + 84)) / 169.0);
        } else if (idx < t0 + t1) {
            int i2 = idx - t0;
            int f = i2 / 85, t = i2 - f*85;
            CM20[i2] = (float)(cos(TWO_PI * (double)((long long)f*t) / 85.0) / 85.0);
        } else if (idx < t0 + t1 + t2) {
            int i2 = idx - t0 - t1;
            int t = i2 / 85, f = i2 - t*85;
            CM1[i2] = (float)cos(TWO_PI * (double)((long long)f*(t + 42)) / 85.0);
        } else {
            int i2 = idx - t0 - t1 - t2;
            int f = i2 / 43, t = i2 - f*43;
            CM21[i2] = (float)(cos(TWO_PI * (double)((long long)f*t) / 43.0) / 43.0);
        }
    }
}

// ---------------- x1: exp-gated interleave, drop last ----------------
__global__ void x1_kernel(const float* __restrict__ cv, float* __restrict__ x1, int m, int ne2) {
    size_t total = (size_t)NB*NC*m;
    for (size_t idx = (size_t)blockIdx.x*blockDim.x + threadIdx.x; idx < total;
         idx += (size_t)gridDim.x*blockDim.x) {
        int t = (int)(idx % m);
        size_t bc = idx / m;
        const float* c2 = cv + bc*ne2;
        x1[idx] = c2[t ^ 1] * expf(c2[t]);
    }
}

// ---------------- GEMM params ----------------
struct GemmP {
    const float* A; int lda;
    const float* Bp; int ldb; long long sBb;
    float* D; long long sDb; int ldd;
    const float* bias;
    int M, N, K;
    int npos;
    int pad, lhalf, inner;
    int kt, mklen;
};

__device__ __forceinline__ uint32_t f2tf32(float v) {
    uint32_t u;
    asm("cvt.rna.tf32.f32 %0, %1;" : "=r"(u) : "f"(v));
    return u;
}
__device__ __forceinline__ void mma_tf32(float c[4], const uint32_t a[4], const uint32_t b[2]) {
    asm("mma.sync.aligned.m16n8k8.row.col.f32.tf32.tf32.f32 "
        "{%0,%1,%2,%3},{%4,%5,%6,%7},{%8,%9},{%0,%1,%2,%3};"
        : "+f"(c[0]), "+f"(c[1]), "+f"(c[2]), "+f"(c[3])
        : "r"(a[0]), "r"(a[1]), "r"(a[2]), "r"(a[3]), "r"(b[0]), "r"(b[1]));
}

template<int BMODE, int KK>
__device__ __forceinline__ float ldB(const GemmP& p, const float* bbase, int sb, int gk) {
    if (gk >= p.K) return 0.f;
    if (BMODE == 0) return bbase[(long long)gk * p.ldb];
    int cin = gk / KK, t = gk - cin*KK;
    if (BMODE == 1) {
        int s = sb + t;
        return (s >= 0 && s < p.lhalf) ? bbase[(long long)cin*p.inner + 2*s] : 0.f;
    }
    return bbase[(long long)cin*p.inner + t];
}

// tf32 mma.sync GEMM, fragment-major smem, register double-buffered fills.
// BMODE: 0 dense, 1 conv-im2col(even/odd), 2 iso-im2col   (KK: conv kernel size)
// BIASM: 0 none, 1 per-row, 2 per-col(q), 3 bias[row/kt]
// ACT:   0 none, 1 tanh, 2 relu
// SMODE: 0 normal, 1 transconv scatter
// Requires: M % BM == 0.
template<int BM, int BN, int BMODE, int KK, int BIASM, int ACT, int SMODE>
__global__ void __launch_bounds__(256)
gemm_k(GemmP p) {
    constexpr int BK = 32;
    constexpr int WR = BM/32;        // warp rows
    constexpr int WC = 8/WR;         // warp cols
    constexpr int WN = BN/WC;        // per-warp N extent
    constexpr int NF = WN/8;         // n fragments per warp
    constexpr int AG = BM/32;        // A fill groups per thread (4 elems each)
    constexpr int BR = BN/32;        // B fill reps per thread (4 elems each)
    __shared__ __align__(16) float As[BM*BK];   // fragment-major
    __shared__ __align__(16) float Bs[BK*BN];   // fragment-major

    const int tid = threadIdx.x, lane = tid & 31, warp = tid >> 5;
    const int wr = warp % WR, wc = warp / WR;
    const int m0 = blockIdx.y * BM, n0 = blockIdx.x * BN;

    // ---- hoisted fill bases ----
    // A fill: groups g: m = (tid>>3) + 32*g, k = (tid&7)*4 + j
    const int am_ = tid >> 3, ak_ = (tid & 7) * 4;
    const float* arow[AG];
    #pragma unroll
    for (int g = 0; g < AG; g++)
        arow[g] = p.A + (long long)(m0 + am_ + 32*g) * p.lda;
    // B fill: reps r: n = (tid&31) + 32*r, k = (tid>>5)*4 + j
    const int bn_ = tid & 31, bk_ = (tid >> 5) * 4;
    const float* bbase_r[BR];
    int sb_r[BR];
    bool nv_r[BR];
    #pragma unroll
    for (int rp = 0; rp < BR; rp++) {
        int gn = n0 + bn_ + 32*rp;
        nv_r[rp] = gn < p.N;
        int g = nv_r[rp] ? gn : 0;
        int b = 0, q = g;
        if (!(BMODE == 0 && p.sBb == 0)) { b = g / p.npos; q = g - b*p.npos; }
        int sb = 0;
        const float* bb;
        if (BMODE == 0) bb = p.Bp + b*p.sBb + q;
        else if (BMODE == 1) { int o = q >> 1, pb = q & 1; sb = o*KK - p.pad; bb = p.Bp + b*p.sBb + pb; }
        else bb = p.Bp + b*p.sBb + q;
        bbase_r[rp] = bb;
        sb_r[rp] = sb;
    }

    // ---- precomputed smem store indices (k-invariant) ----
    // A elem (m, kl): kc=kl>>3, kin=kl&7; wr_=m>>5; mi=(m&31)>>4; mr=m&15
    //   idx = (((kc*WR + wr_)*2 + mi)*32 + (mr&7)*4 + (kin&3))*4 + (mr>>3) + 2*(kin>>2)
    int aidx[AG][4];
    #pragma unroll
    for (int g = 0; g < AG; g++) {
        int m = am_ + 32*g;
        int wr_ = m >> 5, mi = (m & 31) >> 4, mr = m & 15;
        #pragma unroll
        for (int j = 0; j < 4; j++) {
            int kl = ak_ + j;
            int kc = kl >> 3, kin = kl & 7;
            aidx[g][j] = (((kc*WR + wr_)*2 + mi)*32 + (mr & 7)*4 + (kin & 3))*4
                         + (mr >> 3) + 2*(kin >> 2);
        }
    }
    // B elem (kl, n): idx = ((kc*(BN/8) + (n>>3))*32 + (n&7)*4 + (kin&3))*2 + (kin>>2)
    int bidx[BR][4];
    #pragma unroll
    for (int rp = 0; rp < BR; rp++) {
        int n = bn_ + 32*rp;
        #pragma unroll
        for (int j = 0; j < 4; j++) {
            int kl = bk_ + j;
            int kc = kl >> 3, kin = kl & 7;
            bidx[rp][j] = ((kc*(BN/8) + (n >> 3))*32 + (n & 7)*4 + (kin & 3))*2 + (kin >> 2);
        }
    }

    float acc[2][NF][4];
    #pragma unroll
    for (int mi = 0; mi < 2; mi++)
        #pragma unroll
        for (int ni = 0; ni < NF; ni++)
            #pragma unroll
            for (int e = 0; e < 4; e++) acc[mi][ni][e] = 0.f;

    float ra[AG][4], rb[BR][4];
    // prefetch tile 0
    #pragma unroll
    for (int g = 0; g < AG; g++)
        #pragma unroll
        for (int j = 0; j < 4; j++) {
            int gk = ak_ + j;
            ra[g][j] = (gk < p.K) ? arow[g][gk] : 0.f;
        }
    #pragma unroll
    for (int rp = 0; rp < BR; rp++)
        #pragma unroll
        for (int j = 0; j < 4; j++)
            rb[rp][j] = nv_r[rp] ? ldB<BMODE, KK>(p, bbase_r[rp], sb_r[rp], bk_ + j) : 0.f;

    for (int k0 = 0; k0 < p.K; k0 += BK) {
        __syncthreads();
        // store staged regs -> smem (tf32-rounded)
        #pragma unroll
        for (int g = 0; g < AG; g++)
            #pragma unroll
            for (int j = 0; j < 4; j++)
                As[aidx[g][j]] = __uint_as_float(f2tf32(ra[g][j]));
        #pragma unroll
        for (int rp = 0; rp < BR; rp++)
            #pragma unroll
            for (int j = 0; j < 4; j++)
                Bs[bidx[rp][j]] = __uint_as_float(f2tf32(rb[rp][j]));
        __syncthreads();
        // prefetch next tile into regs (overlaps with compute below)
        int kn = k0 + BK;
        if (kn < p.K) {
            #pragma unroll
            for (int g = 0; g < AG; g++)
                #pragma unroll
                for (int j = 0; j < 4; j++) {
                    int gk = kn + ak_ + j;
                    ra[g][j] = (gk < p.K) ? arow[g][gk] : 0.f;
                }
            #pragma unroll
            for (int rp = 0; rp < BR; rp++)
                #pragma unroll
                for (int j = 0; j < 4; j++)
                    rb[rp][j] = nv_r[rp] ? ldB<BMODE, KK>(p, bbase_r[rp], sb_r[rp], kn + bk_ + j) : 0.f;
        }
        // compute from fragment-major smem
        #pragma unroll
        for (int kc = 0; kc < 4; kc++) {
            uint32_t af[2][4];
            #pragma unroll
            for (int mi = 0; mi < 2; mi++) {
                const float4 av = *(const float4*)&As[(((kc*WR + wr)*2 + mi)*32 + lane)*4];
                af[mi][0] = __float_as_uint(av.x);
                af[mi][1] = __float_as_uint(av.y);
                af[mi][2] = __float_as_uint(av.z);
                af[mi][3] = __float_as_uint(av.w);
            }
            uint32_t bf[NF][2];
            #pragma unroll
            for (int ni = 0; ni < NF; ni++) {
                const float2 bv = *(const float2*)&Bs[((kc*(BN/8) + wc*(WN/8) + ni)*32 + lane)*2];
                bf[ni][0] = __float_as_uint(bv.x);
                bf[ni][1] = __float_as_uint(bv.y);
            }
            #pragma unroll
            for (int mi = 0; mi < 2; mi++)
                #pragma unroll
                for (int ni = 0; ni < NF; ni++)
                    mma_tf32(acc[mi][ni], af[mi], bf[ni]);
        }
    }

    // ---- epilogue ----
    #pragma unroll
    for (int mi = 0; mi < 2; mi++) {
        #pragma unroll
        for (int half = 0; half < 2; half++) {
            int row = m0 + wr*32 + mi*16 + (lane >> 2) + half*8;
            float brow = 0.f;
            if (BIASM == 1) brow = p.bias[row];
            else if (BIASM == 3) brow = p.bias[row / p.kt];
            int cout = 0, jj = 0;
            if (SMODE == 1) { cout = row / p.kt; jj = row - cout*p.kt; }
            #pragma unroll
            for (int ni = 0; ni < NF; ni++) {
                #pragma unroll
                for (int e = 0; e < 2; e++) {
                    int gn = n0 + wc*WN + ni*8 + (lane & 3)*2 + e;
                    if (gn >= p.N) continue;
                    int b, q;
                    if (SMODE == 0 && p.sDb == 0) { b = 0; q = gn; }
                    else { b = gn / p.npos; q = gn - b*p.npos; }
                    float v = acc[mi][ni][half*2 + e] + brow;
                    if (BIASM == 2) v += p.bias[q];
                    if (ACT == 1) v = tanhf(v);
                    else if (ACT == 2) v = fmaxf(v, 0.f);
                    long long addr;
                    if (SMODE == 0) addr = b*p.sDb + (long long)row*p.ldd + q;
                    else addr = b*p.sDb + (long long)cout*p.mklen + (long long)q*p.kt + jj;
                    p.D[addr] = v;
                }
            }
        }
    }
}

// ---------------- block reduce + layer norms ----------
__device__ __forceinline__ float blk_sum(float v) {
    __shared__ float sb[8];
    #pragma unroll
    for (int o = 16; o; o >>= 1) v += __shfl_xor_sync(0xffffffffu, v, o);
    if ((threadIdx.x & 31) == 0) sb[threadIdx.x >> 5] = v;
    __syncthreads();
    float t = 0.f;
    #pragma unroll
    for (int i = 0; i < 8; i++) t += sb[i];
    __syncthreads();
    return t;
}

__global__ void ln1_kernel(const float* __restrict__ xr, const float* __restrict__ x1,
                           const float* __restrict__ g, const float* __restrict__ bt,
                           float* __restrict__ out, int m) {
    int row = blockIdx.x;
    int b = row / m, t = row - b*m;
    int tid = threadIdx.x;
    size_t base = (size_t)b*NC*m + t;
    float v0 = xr[base + (size_t)tid*m]       + x1[base + (size_t)tid*m];
    float v1 = xr[base + (size_t)(tid+256)*m] + x1[base + (size_t)(tid+256)*m];
    float mu = blk_sum(v0 + v1) * (1.f/NC);
    float d0 = v0 - mu, d1 = v1 - mu;
    float var = blk_sum(d0*d0 + d1*d1) * (1.f/NC);
    float inv = rsqrtf(var + 1e-5f);
    out[base + (size_t)tid*m]       = d0*inv*g[tid]     + bt[tid];
    out[base + (size_t)(tid+256)*m] = d1*inv*g[tid+256] + bt[tid+256];
}

__global__ void branch_out_kernel(const float* __restrict__ y2, const float* __restrict__ resn,
                                  const float* __restrict__ g, const float* __restrict__ bt,
                                  float* __restrict__ br, int mk, int nbr) {
    int row = blockIdx.x;
    int b = row >> 10, l = row & 1023;
    int li = (l * mk) >> 10;
    int tid = threadIdx.x;
    size_t yb = (size_t)b*NC*mk + li;
    size_t rb = (size_t)b*NC*NL + l;
    float v0 = y2[yb + (size_t)tid*mk]       + resn[rb + (size_t)tid*NL];
    float v1 = y2[yb + (size_t)(tid+256)*mk] + resn[rb + (size_t)(tid+256)*NL];
    float mu = blk_sum(v0 + v1) * (1.f/NC);
    float d0 = v0 - mu, d1 = v1 - mu;
    float var = blk_sum(d0*d0 + d1*d1) * (1.f/NC);
    float inv = rsqrtf(var + 1e-5f);
    float* o = br + (size_t)row*(2*NC) + nbr*NC;
    o[tid]     = d0*inv*g[tid]     + bt[tid];
    o[tid+256] = d1*inv*g[tid+256] + bt[tid+256];
}

__global__ void final_ln_kernel(const float* __restrict__ mg, const float* __restrict__ h2,
                                const float* __restrict__ g, const float* __restrict__ bt,
                                float* __restrict__ out) {
    int row = blockIdx.x;
    int tid = threadIdx.x;
    size_t base = (size_t)row*NC;
    float v0 = mg[base + tid]       + h2[base + tid];
    float v1 = mg[base + tid + 256] + h2[base + tid + 256];
    float mu = blk_sum(v0 + v1) * (1.f/NC);
    float d0 = v0 - mu, d1 = v1 - mu;
    float var = blk_sum(d0*d0 + d1*d1) * (1.f/NC);
    float inv = rsqrtf(var + 1e-5f);
    out[base + tid]       = d0*inv*g[tid]     + bt[tid];
    out[base + tid + 256] = d1*inv*g[tid+256] + bt[tid+256];
}

template<int BM, int BN>
static inline dim3 gg(int M, int N) { return dim3((N + BN - 1)/BN, M/BM, 1); }

extern "C" void kernel_launch(void* const* d_in, const int* in_sizes, int n_in,
                              void* d_out, int out_size) {
    (void)in_sizes; (void)n_in; (void)out_size;
    const float* src   = (const float*)d_in[0];
    const float* cw[2] = {(const float*)d_in[1],  (const float*)d_in[7]};
    const float* cb[2] = {(const float*)d_in[2],  (const float*)d_in[8]};
    const float* iw[2] = {(const float*)d_in[3],  (const float*)d_in[9]};
    const float* ib[2] = {(const float*)d_in[4],  (const float*)d_in[10]};
    const float* tw[2] = {(const float*)d_in[5],  (const float*)d_in[11]};
    const float* tb[2] = {(const float*)d_in[6],  (const float*)d_in[12]};
    const float* mw  = (const float*)d_in[13];
    const float* mb  = (const float*)d_in[14];
    const float* ng  = (const float*)d_in[15];
    const float* nb  = (const float*)d_in[16];
    const float* fw1 = (const float*)d_in[17];
    const float* fb1 = (const float*)d_in[18];
    const float* fw2 = (const float*)d_in[19];
    const float* fb2 = (const float*)d_in[20];
    const float* fng = (const float*)d_in[21];
    const float* fnb = (const float*)d_in[22];
    float* out = (float*)d_out;

    float *p_res,*p_cv,*p_x1,*p_xf,*p_xi,*p_xr,*p_yln,*p_y2,*p_br,*p_mg,*p_h1,*p_h2;
    float *p_W2a,*p_W2b,*p_Wm,*p_CM0,*p_CM20,*p_CM1,*p_CM21;
    cudaGetSymbolAddress((void**)&p_res, g_res);
    cudaGetSymbolAddress((void**)&p_cv,  g_cv);
    cudaGetSymbolAddress((void**)&p_x1,  g_x1);
    cudaGetSymbolAddress((void**)&p_xf,  g_xf);
    cudaGetSymbolAddress((void**)&p_xi,  g_xi);
    cudaGetSymbolAddress((void**)&p_xr,  g_xr);
    cudaGetSymbolAddress((void**)&p_yln, g_yln);
    cudaGetSymbolAddress((void**)&p_y2,  g_y2);
    cudaGetSymbolAddress((void**)&p_br,  g_br);
    cudaGetSymbolAddress((void**)&p_mg,  g_mg);
    cudaGetSymbolAddress((void**)&p_h1,  g_h1);
    cudaGetSymbolAddress((void**)&p_h2,  g_h2);
    cudaGetSymbolAddress((void**)&p_W2a, g_W2a);
    cudaGetSymbolAddress((void**)&p_W2b, g_W2b);
    cudaGetSymbolAddress((void**)&p_Wm,  g_Wm);
    cudaGetSymbolAddress((void**)&p_CM0, g_CM0);
    cudaGetSymbolAddress((void**)&p_CM20,g_CM20);
    cudaGetSymbolAddress((void**)&p_CM1, g_CM1);
    cudaGetSymbolAddress((void**)&p_CM21,g_CM21);

    // prep (launches 0-4; launch 5 = first GEMM -> profiled by ncu -s 5)
    decomp_kernel<<<dim3(NL/32, NC/32, NB), dim3(32, 32)>>>(src, p_res);
    prep_merge_k<<<1024, 256>>>(mw, p_Wm);
    prep_trw_k<<<2048, 256>>>(tw[0], p_W2a, 12);
    prep_trw_k<<<4096, 256>>>(tw[1], p_W2b, 24);
    build_cm_all<<<256, 256>>>(p_CM0, p_CM20, p_CM1, p_CM21);

    const int Kk[2] = {12, 24}, PD[2] = {6, 12}, NE[2] = {43, 22},
              MM[2] = {85, 43}, N2_[2] = {169, 85}, MKl[2] = {1020, 1032};
    float* CMv[2]  = {p_CM0, p_CM1};
    float* CM2v[2] = {p_CM20, p_CM21};
    float* W2v[2]  = {p_W2a, p_W2b};

    for (int n = 0; n < 2; n++) {
        int k = Kk[n], pad = PD[n], ne = NE[n], m = MM[n], N2 = N2_[n], mk = MKl[n];
        int ne2 = 2*ne;

        { // strided conv (even+odd interleaved), tanh
            GemmP p{};
            p.A = cw[n]; p.lda = NC*k;
            p.Bp = p_res + (size_t)n*NB*NC*NL; p.sBb = (long long)NC*NL;
            p.pad = pad; p.lhalf = LH; p.inner = NL;
            p.D = p_cv; p.sDb = (long long)NC*ne2; p.ldd = ne2;
            p.bias = cb[n];
            p.M = NC; p.N = NB*ne2; p.K = NC*k; p.npos = ne2;
            if (n == 0) gemm_k<64,128,1,12,1,1,0><<<gg<64,128>(p.M,p.N), 256>>>(p);
            else        gemm_k<64,64, 1,24,1,1,0><<<gg<64,64 >(p.M,p.N), 256>>>(p);
        }
        x1_kernel<<<1024, 256>>>(p_cv, p_x1, m, ne2);
        { // real-DFT
            GemmP p{};
            p.A = p_x1; p.lda = m;
            p.Bp = CMv[n]; p.ldb = N2; p.sBb = 0;
            p.D = p_xf; p.sDb = 0; p.ldd = N2;
            p.M = NB*NC; p.N = N2; p.K = m; p.npos = N2;
            gemm_k<128,64,0,1,0,0,0><<<gg<128,64>(p.M,p.N), 256>>>(p);
        }
        { // isometric conv (valid), tanh
            GemmP p{};
            p.A = iw[n]; p.lda = NC*m;
            p.Bp = p_xf; p.sBb = (long long)NC*N2; p.inner = N2;
            p.D = p_xi; p.sDb = (long long)NC*m; p.ldd = m;
            p.bias = ib[n];
            p.M = NC; p.N = NB*m; p.K = NC*m; p.npos = m;
            if (n == 0) gemm_k<64,128,2,85,1,1,0><<<gg<64,128>(p.M,p.N), 256>>>(p);
            else        gemm_k<64,64, 2,43,1,1,0><<<gg<64,64 >(p.M,p.N), 256>>>(p);
        }
        { // real-IDFT
            GemmP p{};
            p.A = p_xi; p.lda = m;
            p.Bp = CM2v[n]; p.ldb = m; p.sBb = 0;
            p.D = p_xr; p.sDb = 0; p.ldd = m;
            p.M = NB*NC; p.N = m; p.K = m; p.npos = m;
            gemm_k<128,64,0,1,0,0,0><<<gg<128,64>(p.M,p.N), 256>>>(p);
        }
        ln1_kernel<<<NB*m, 256>>>(p_xr, p_x1, ng, nb, p_yln, m);
        { // conv-transpose (stride==kernel), tanh, scatter store
            GemmP p{};
            p.A = W2v[n]; p.lda = NC;
            p.Bp = p_yln; p.ldb = m; p.sBb = (long long)NC*m;
            p.D = p_y2; p.sDb = (long long)NC*mk; p.kt = k; p.mklen = mk;
            p.bias = tb[n];
            p.M = NC*k; p.N = NB*m; p.K = NC; p.npos = m;
            gemm_k<128,128,0,1,3,1,1><<<gg<128,128>(p.M,p.N), 256>>>(p);
        }
        branch_out_kernel<<<NB*NL, 256>>>(p_y2, p_res + (size_t)n*NB*NC*NL, ng, nb, p_br, mk, n);
    }
    { // merge
        GemmP p{};
        p.A = p_br; p.lda = 2*NC;
        p.Bp = p_Wm; p.ldb = NC; p.sBb = 0;
        p.D = p_mg; p.sDb = 0; p.ldd = NC;
        p.bias = mb;
        p.M = NB*NL; p.N = NC; p.K = 2*NC; p.npos = NC;
        gemm_k<128,128,0,1,2,0,0><<<gg<128,128>(p.M,p.N), 256>>>(p);
    }
    { // FFN layer 1 (relu)
        GemmP p{};
        p.A = p_mg; p.lda = NC;
        p.Bp = fw1; p.ldb = 4*NC; p.sBb = 0;
        p.D = p_h1; p.sDb = 0; p.ldd = 4*NC;
        p.bias = fb1;
        p.M = NB*NL; p.N = 4*NC; p.K = NC; p.npos = 4*NC;
        gemm_k<128,128,0,1,2,2,0><<<gg<128,128>(p.M,p.N), 256>>>(p);
    }
    { // FFN layer 2
        GemmP p{};
        p.A = p_h1; p.lda = 4*NC;
        p.Bp = fw2; p.ldb = NC; p.sBb = 0;
        p.D = p_h2; p.sDb = 0; p.ldd = NC;
        p.bias = fb2;
        p.M = NB*NL; p.N = NC; p.K = 4*NC; p.npos = NC;
        gemm_k<128,128,0,1,2,0,0><<<gg<128,128>(p.M,p.N), 256>>>(p);
    }
    final_ln_kernel<<<NB*NL, 256>>>(p_mg, p_h2, fng, fnb, out);
}

// round 6
// speedup vs baseline: 2.2226x; 1.0663x over previous
#include <cuda_runtime.h>
#include <math.h>
#include <stdint.h>

#define NB 32
#define NL 1024
#define NC 512
#define LH 512   // L/2

// ---------------- scratch (device globals; no allocations) ----------------
__device__ float g_res[(size_t)2*NB*NC*NL];     // [2][B][C][L]
__device__ float g_cv [(size_t)2*NB*NC*86];     // conv out interleaved, per branch
__device__ float g_x1 [(size_t)NB*NC*85];       // [B][C][m]
__device__ float g_xf [(size_t)NB*NC*169];      // [B][C][2m-1]
__device__ float g_xi [(size_t)NB*NC*85];
__device__ float g_xr [(size_t)NB*NC*85];
__device__ float g_yln[(size_t)NB*NC*85];
__device__ float g_y2 [(size_t)NB*NC*1032];     // [B][C][m*k]
__device__ float g_br [(size_t)NB*NL*2*NC];     // [B*L][2*C]
__device__ float g_mg [(size_t)NB*NL*NC];
__device__ float g_h1 [(size_t)NB*NL*4*NC];
__device__ float g_h2 [(size_t)NB*NL*NC];
__device__ float g_W2a[(size_t)NC*12*NC];
__device__ float g_W2b[(size_t)NC*24*NC];
__device__ float g_Wm [(size_t)2*NC*NC];
__device__ float g_CM0 [85*169];
__device__ float g_CM20[85*85];
__device__ float g_CM1 [43*85];
__device__ float g_CM21[43*43];

// ---------------- series decomp ----------------
__global__ void decomp_kernel(const float* __restrict__ src, float* __restrict__ res) {
    __shared__ float s[64][33];
    int b = blockIdx.z;
    int c0 = blockIdx.y * 32;
    int l0 = blockIdx.x * 32;
    int tx = threadIdx.x, ty = threadIdx.y;
    for (int r = ty; r < 64; r += 32) {
        int l = l0 - 16 + r;
        l = l < 0 ? 0 : (l > NL - 1 ? NL - 1 : l);
        s[r][tx] = src[((size_t)b*NL + l)*NC + c0 + tx];
    }
    __syncthreads();
    int base = tx + 16;
    float s17 = 0.f;
    #pragma unroll
    for (int j = -8; j <= 8; j++) s17 += s[base + j][ty];
    float s33 = s17;
    #pragma unroll
    for (int j = 9; j <= 16; j++) s33 += s[base - j][ty] + s[base + j][ty];
    float v = s[base][ty];
    size_t o = ((size_t)(b*NC + c0 + ty))*NL + l0 + tx;
    res[o] = v - s17 / 17.0f;
    res[(size_t)NB*NC*NL + o] = v - s33 / 33.0f;
}

// ---------------- fused prep: merge-w transpose + trw transposes + DFT mats ----
__global__ void prep_all(const float* __restrict__ mwt, float* __restrict__ Wm,
                         const float* __restrict__ tw0, float* __restrict__ W2a,
                         const float* __restrict__ tw1, float* __restrict__ W2b,
                         float* __restrict__ CM0, float* __restrict__ CM20,
                         float* __restrict__ CM1, float* __restrict__ CM21) {
    const double TWO_PI = 6.283185307179586476925286766559;
    const int tM = NC*NC*2;
    const int tA = NC*NC*12, tB = NC*NC*24;
    const int c0 = 85*169, c1 = 85*85, c2 = 43*85, c3 = 43*43;
    int total = tM + tA + tB + c0 + c1 + c2 + c3;
    for (int idx = blockIdx.x*blockDim.x + threadIdx.x; idx < total; idx += gridDim.x*blockDim.x) {
        int i = idx;
        if (i < tM) {
            int o = i / (NC*2);
            int rem = i - o*NC*2;
            int c = rem >> 1, n = rem & 1;
            Wm[((size_t)n*NC + c)*NC + o] = mwt[i];
            continue;
        }
        i -= tM;
        if (i < tA) {
            int cin = i / (NC*12);
            int r   = i - cin*(NC*12);
            W2a[(size_t)r*NC + cin] = tw0[i];
            continue;
        }
        i -= tA;
        if (i < tB) {
            int cin = i / (NC*24);
            int r   = i - cin*(NC*24);
            W2b[(size_t)r*NC + cin] = tw1[i];
            continue;
        }
        i -= tB;
        if (i < c0) {
            int t = i / 169, f = i - t*169;
            CM0[i] = (float)cos(TWO_PI * (double)((long long)f*(t + 84)) / 169.0);
            continue;
        }
        i -= c0;
        if (i < c1) {
            int f = i / 85, t = i - f*85;
            CM20[i] = (float)(cos(TWO_PI * (double)((long long)f*t) / 85.0) / 85.0);
            continue;
        }
        i -= c1;
        if (i < c2) {
            int t = i / 85, f = i - t*85;
            CM1[i] = (float)cos(TWO_PI * (double)((long long)f*(t + 42)) / 85.0);
            continue;
        }
        i -= c2;
        {
            int f = i / 43, t = i - f*43;
            CM21[i] = (float)(cos(TWO_PI * (double)((long long)f*t) / 43.0) / 43.0);
        }
    }
}

// ---------------- x1: exp-gated interleave, drop last ----------------
__global__ void x1_kernel(const float* __restrict__ cv, float* __restrict__ x1, int m, int ne2) {
    size_t total = (size_t)NB*NC*m;
    for (size_t idx = (size_t)blockIdx.x*blockDim.x + threadIdx.x; idx < total;
         idx += (size_t)gridDim.x*blockDim.x) {
        int t = (int)(idx % m);
        size_t bc = idx / m;
        const float* c2 = cv + bc*ne2;
        x1[idx] = c2[t ^ 1] * expf(c2[t]);
    }
}

// ---------------- GEMM params ----------------
struct GemmP {
    const float* A; int lda;
    const float* Bp; int ldb; long long sBb;
    float* D; long long sDb; int ldd;
    const float* bias;
    int M, N, K;
    int npos;
    int pad, lhalf, inner;
    int kt, mklen;
};

__device__ __forceinline__ uint32_t f2tf32(float v) {
    uint32_t u;
    asm("cvt.rna.tf32.f32 %0, %1;" : "=r"(u) : "f"(v));
    return u;
}
__device__ __forceinline__ void mma_tf32(float c[4], const uint32_t a[4], const uint32_t b[2]) {
    asm("mma.sync.aligned.m16n8k8.row.col.f32.tf32.tf32.f32 "
        "{%0,%1,%2,%3},{%4,%5,%6,%7},{%8,%9},{%0,%1,%2,%3};"
        : "+f"(c[0]), "+f"(c[1]), "+f"(c[2]), "+f"(c[3])
        : "r"(a[0]), "r"(a[1]), "r"(a[2]), "r"(a[3]), "r"(b[0]), "r"(b[1]));
}

template<int BMODE, int KK>
__device__ __forceinline__ float ldB(const GemmP& p, const float* bbase, int sb, int gk) {
    if (gk >= p.K) return 0.f;
    if (BMODE == 0) return bbase[(long long)gk * p.ldb];
    int cin = gk / KK, t = gk - cin*KK;
    if (BMODE == 1) {
        int s = sb + t;
        return (s >= 0 && s < p.lhalf) ? bbase[(long long)cin*p.inner + 2*s] : 0.f;
    }
    return bbase[(long long)cin*p.inner + t];
}

// tf32 mma.sync GEMM, fragment-major smem, DOUBLE-BUFFERED, 1 sync/slab.
// BMODE: 0 dense, 1 conv-im2col(even/odd), 2 iso-im2col   (KK: conv kernel size)
// BIASM: 0 none, 1 per-row, 2 per-col(q), 3 bias[row/kt]
// ACT:   0 none, 1 tanh, 2 relu
// SMODE: 0 normal, 1 transconv scatter
// Requires: M % BM == 0.
template<int BM, int BN, int BMODE, int KK, int BIASM, int ACT, int SMODE>
__global__ void __launch_bounds__(256)
gemm_k(GemmP p) {
    constexpr int BK = 32;
    constexpr int WR = BM/32;        // warp rows
    constexpr int WC = 8/WR;         // warp cols
    constexpr int WN = BN/WC;        // per-warp N extent
    constexpr int NF = WN/8;         // n fragments per warp
    constexpr int AG = BM/32;        // A fill groups per thread (4 elems each)
    constexpr int BR = BN/32;        // B fill reps per thread (4 elems each)
    constexpr int ASZ = BM*BK, BSZ = BK*BN;
    extern __shared__ float dyn[];
    float* As = dyn;                 // [2][ASZ]
    float* Bs = dyn + 2*ASZ;         // [2][BSZ]

    const int tid = threadIdx.x, lane = tid & 31, warp = tid >> 5;
    const int wr = warp % WR, wc = warp / WR;
    const int m0 = blockIdx.y * BM, n0 = blockIdx.x * BN;

    // ---- hoisted fill bases ----
    const int am_ = tid >> 3, ak_ = (tid & 7) * 4;
    const float* arow[AG];
    #pragma unroll
    for (int g = 0; g < AG; g++)
        arow[g] = p.A + (long long)(m0 + am_ + 32*g) * p.lda;
    const int bn_ = tid & 31, bk_ = (tid >> 5) * 4;
    const float* bbase_r[BR];
    int sb_r[BR];
    bool nv_r[BR];
    #pragma unroll
    for (int rp = 0; rp < BR; rp++) {
        int gn = n0 + bn_ + 32*rp;
        nv_r[rp] = gn < p.N;
        int g = nv_r[rp] ? gn : 0;
        int b = 0, q = g;
        if (!(BMODE == 0 && p.sBb == 0)) { b = g / p.npos; q = g - b*p.npos; }
        int sb = 0;
        const float* bb;
        if (BMODE == 0) bb = p.Bp + b*p.sBb + q;
        else if (BMODE == 1) { int o = q >> 1, pb = q & 1; sb = o*KK - p.pad; bb = p.Bp + b*p.sBb + pb; }
        else bb = p.Bp + b*p.sBb + q;
        bbase_r[rp] = bb;
        sb_r[rp] = sb;
    }

    // ---- base-only smem store indices (j-step: A +4, B +2) ----
    int aidx[AG];
    #pragma unroll
    for (int g = 0; g < AG; g++) {
        int m = am_ + 32*g;
        int wr_ = m >> 5, mi = (m & 31) >> 4, mr = m & 15;
        int kc = ak_ >> 3, kin = ak_ & 7;
        aidx[g] = (((kc*WR + wr_)*2 + mi)*32 + (mr & 7)*4 + (kin & 3))*4
                  + (mr >> 3) + 2*(kin >> 2);
    }
    int bidx[BR];
    #pragma unroll
    for (int rp = 0; rp < BR; rp++) {
        int n = bn_ + 32*rp;
        int kc = bk_ >> 3, kin = bk_ & 7;
        bidx[rp] = ((kc*(BN/8) + (n >> 3))*32 + (n & 7)*4 + (kin & 3))*2 + (kin >> 2);
    }

    float acc[2][NF][4];
    #pragma unroll
    for (int mi = 0; mi < 2; mi++)
        #pragma unroll
        for (int ni = 0; ni < NF; ni++)
            #pragma unroll
            for (int e = 0; e < 4; e++) acc[mi][ni][e] = 0.f;

    float ra[AG][4], rb[BR][4];
    // prefetch tile 0 and store to buffer 0
    #pragma unroll
    for (int g = 0; g < AG; g++)
        #pragma unroll
        for (int j = 0; j < 4; j++) {
            int gk = ak_ + j;
            ra[g][j] = (gk < p.K) ? arow[g][gk] : 0.f;
        }
    #pragma unroll
    for (int rp = 0; rp < BR; rp++)
        #pragma unroll
        for (int j = 0; j < 4; j++)
            rb[rp][j] = nv_r[rp] ? ldB<BMODE, KK>(p, bbase_r[rp], sb_r[rp], bk_ + j) : 0.f;
    #pragma unroll
    for (int g = 0; g < AG; g++)
        #pragma unroll
        for (int j = 0; j < 4; j++)
            As[aidx[g] + 4*j] = __uint_as_float(f2tf32(ra[g][j]));
    #pragma unroll
    for (int rp = 0; rp < BR; rp++)
        #pragma unroll
        for (int j = 0; j < 4; j++)
            Bs[bidx[rp] + 2*j] = __uint_as_float(f2tf32(rb[rp][j]));
    __syncthreads();

    int buf = 0;
    for (int k0 = 0; k0 < p.K; k0 += BK) {
        int kn = k0 + BK;
        bool more = kn < p.K;
        // prefetch next slab into regs (LDG issues early, overlaps MMAs)
        if (more) {
            #pragma unroll
            for (int g = 0; g < AG; g++)
                #pragma unroll
                for (int j = 0; j < 4; j++) {
                    int gk = kn + ak_ + j;
                    ra[g][j] = (gk < p.K) ? arow[g][gk] : 0.f;
                }
            #pragma unroll
            for (int rp = 0; rp < BR; rp++)
                #pragma unroll
                for (int j = 0; j < 4; j++)
                    rb[rp][j] = nv_r[rp] ? ldB<BMODE, KK>(p, bbase_r[rp], sb_r[rp], kn + bk_ + j) : 0.f;
        }
        // compute current slab
        const float* Ac = As + buf*ASZ;
        const float* Bc = Bs + buf*BSZ;
        #pragma unroll
        for (int kc = 0; kc < 4; kc++) {
            uint32_t af[2][4];
            #pragma unroll
            for (int mi = 0; mi < 2; mi++) {
                const float4 av = *(const float4*)&Ac[(((kc*WR + wr)*2 + mi)*32 + lane)*4];
                af[mi][0] = __float_as_uint(av.x);
                af[mi][1] = __float_as_uint(av.y);
                af[mi][2] = __float_as_uint(av.z);
                af[mi][3] = __float_as_uint(av.w);
            }
            uint32_t bf[NF][2];
            #pragma unroll
            for (int ni = 0; ni < NF; ni++) {
                const float2 bv = *(const float2*)&Bc[((kc*(BN/8) + wc*(WN/8) + ni)*32 + lane)*2];
                bf[ni][0] = __float_as_uint(bv.x);
                bf[ni][1] = __float_as_uint(bv.y);
            }
            #pragma unroll
            for (int mi = 0; mi < 2; mi++)
                #pragma unroll
                for (int ni = 0; ni < NF; ni++)
                    mma_tf32(acc[mi][ni], af[mi], bf[ni]);
        }
        // store next slab into other buffer
        if (more) {
            float* An = As + (buf^1)*ASZ;
            float* Bn = Bs + (buf^1)*BSZ;
            #pragma unroll
            for (int g = 0; g < AG; g++)
                #pragma unroll
                for (int j = 0; j < 4; j++)
                    An[aidx[g] + 4*j] = __uint_as_float(f2tf32(ra[g][j]));
            #pragma unroll
            for (int rp = 0; rp < BR; rp++)
                #pragma unroll
                for (int j = 0; j < 4; j++)
                    Bn[bidx[rp] + 2*j] = __uint_as_float(f2tf32(rb[rp][j]));
        }
        __syncthreads();
        buf ^= 1;
    }

    // ---- epilogue ----
    #pragma unroll
    for (int mi = 0; mi < 2; mi++) {
        #pragma unroll
        for (int half = 0; half < 2; half++) {
            int row = m0 + wr*32 + mi*16 + (lane >> 2) + half*8;
            float brow = 0.f;
            if (BIASM == 1) brow = p.bias[row];
            else if (BIASM == 3) brow = p.bias[row / p.kt];
            int cout = 0, jj = 0;
            if (SMODE == 1) { cout = row / p.kt; jj = row - cout*p.kt; }
            #pragma unroll
            for (int ni = 0; ni < NF; ni++) {
                #pragma unroll
                for (int e = 0; e < 2; e++) {
                    int gn = n0 + wc*WN + ni*8 + (lane & 3)*2 + e;
                    if (gn >= p.N) continue;
                    int b, q;
                    if (SMODE == 0 && p.sDb == 0) { b = 0; q = gn; }
                    else { b = gn / p.npos; q = gn - b*p.npos; }
                    float v = acc[mi][ni][half*2 + e] + brow;
                    if (BIASM == 2) v += p.bias[q];
                    if (ACT == 1) v = tanhf(v);
                    else if (ACT == 2) v = fmaxf(v, 0.f);
                    long long addr;
                    if (SMODE == 0) addr = b*p.sDb + (long long)row*p.ldd + q;
                    else addr = b*p.sDb + (long long)cout*p.mklen + (long long)q*p.kt + jj;
                    p.D[addr] = v;
                }
            }
        }
    }
}

// ---------------- block reduce + layer norms ----------
__device__ __forceinline__ float blk_sum(float v) {
    __shared__ float sb[8];
    #pragma unroll
    for (int o = 16; o; o >>= 1) v += __shfl_xor_sync(0xffffffffu, v, o);
    if ((threadIdx.x & 31) == 0) sb[threadIdx.x >> 5] = v;
    __syncthreads();
    float t = 0.f;
    #pragma unroll
    for (int i = 0; i < 8; i++) t += sb[i];
    __syncthreads();
    return t;
}

__global__ void ln1_kernel(const float* __restrict__ xr, const float* __restrict__ x1,
                           const float* __restrict__ g, const float* __restrict__ bt,
                           float* __restrict__ out, int m) {
    int row = blockIdx.x;
    int b = row / m, t = row - b*m;
    int tid = threadIdx.x;
    size_t base = (size_t)b*NC*m + t;
    float v0 = xr[base + (size_t)tid*m]       + x1[base + (size_t)tid*m];
    float v1 = xr[base + (size_t)(tid+256)*m] + x1[base + (size_t)(tid+256)*m];
    float mu = blk_sum(v0 + v1) * (1.f/NC);
    float d0 = v0 - mu, d1 = v1 - mu;
    float var = blk_sum(d0*d0 + d1*d1) * (1.f/NC);
    float inv = rsqrtf(var + 1e-5f);
    out[base + (size_t)tid*m]       = d0*inv*g[tid]     + bt[tid];
    out[base + (size_t)(tid+256)*m] = d1*inv*g[tid+256] + bt[tid+256];
}

__global__ void branch_out_kernel(const float* __restrict__ y2, const float* __restrict__ resn,
                                  const float* __restrict__ g, const float* __restrict__ bt,
                                  float* __restrict__ br, int mk, int nbr) {
    int row = blockIdx.x;
    int b = row >> 10, l = row & 1023;
    int li = (l * mk) >> 10;
    int tid = threadIdx.x;
    size_t yb = (size_t)b*NC*mk + li;
    size_t rb = (size_t)b*NC*NL + l;
    float v0 = y2[yb + (size_t)tid*mk]       + resn[rb + (size_t)tid*NL];
    float v1 = y2[yb + (size_t)(tid+256)*mk] + resn[rb + (size_t)(tid+256)*NL];
    float mu = blk_sum(v0 + v1) * (1.f/NC);
    float d0 = v0 - mu, d1 = v1 - mu;
    float var = blk_sum(d0*d0 + d1*d1) * (1.f/NC);
    float inv = rsqrtf(var + 1e-5f);
    float* o = br + (size_t)row*(2*NC) + nbr*NC;
    o[tid]     = d0*inv*g[tid]     + bt[tid];
    o[tid+256] = d1*inv*g[tid+256] + bt[tid+256];
}

__global__ void final_ln_kernel(const float* __restrict__ mg, const float* __restrict__ h2,
                                const float* __restrict__ g, const float* __restrict__ bt,
                                float* __restrict__ out) {
    int row = blockIdx.x;
    int tid = threadIdx.x;
    size_t base = (size_t)row*NC;
    float v0 = mg[base + tid]       + h2[base + tid];
    float v1 = mg[base + tid + 256] + h2[base + tid + 256];
    float mu = blk_sum(v0 + v1) * (1.f/NC);
    float d0 = v0 - mu, d1 = v1 - mu;
    float var = blk_sum(d0*d0 + d1*d1) * (1.f/NC);
    float inv = rsqrtf(var + 1e-5f);
    out[base + tid]       = d0*inv*g[tid]     + bt[tid];
    out[base + tid + 256] = d1*inv*g[tid+256] + bt[tid+256];
}

template<int BM, int BN>
static inline dim3 gg(int M, int N) { return dim3((N + BN - 1)/BN, M/BM, 1); }

template<int BM, int BN, int BMODE, int KK, int BIASM, int ACT, int SMODE>
static void launch_gemm(const GemmP& p) {
    constexpr int SMEM = 2*(BM*32 + 32*BN)*4;
    if (SMEM > 48*1024)
        cudaFuncSetAttribute((const void*)gemm_k<BM,BN,BMODE,KK,BIASM,ACT,SMODE>,
                             cudaFuncAttributeMaxDynamicSharedMemorySize, SMEM);
    gemm_k<BM,BN,BMODE,KK,BIASM,ACT,SMODE><<<gg<BM,BN>(p.M, p.N), 256, SMEM>>>(p);
}

extern "C" void kernel_launch(void* const* d_in, const int* in_sizes, int n_in,
                              void* d_out, int out_size) {
    (void)in_sizes; (void)n_in; (void)out_size;
    const float* src   = (const float*)d_in[0];
    const float* cw[2] = {(const float*)d_in[1],  (const float*)d_in[7]};
    const float* cb[2] = {(const float*)d_in[2],  (const float*)d_in[8]};
    const float* iw[2] = {(const float*)d_in[3],  (const float*)d_in[9]};
    const float* ib[2] = {(const float*)d_in[4],  (const float*)d_in[10]};
    const float* tw[2] = {(const float*)d_in[5],  (const float*)d_in[11]};
    const float* tb[2] = {(const float*)d_in[6],  (const float*)d_in[12]};
    const float* mw  = (const float*)d_in[13];
    const float* mb  = (const float*)d_in[14];
    const float* ng  = (const float*)d_in[15];
    const float* nb  = (const float*)d_in[16];
    const float* fw1 = (const float*)d_in[17];
    const float* fb1 = (const float*)d_in[18];
    const float* fw2 = (const float*)d_in[19];
    const float* fb2 = (const float*)d_in[20];
    const float* fng = (const float*)d_in[21];
    const float* fnb = (const float*)d_in[22];
    float* out = (float*)d_out;

    float *p_res,*p_cv,*p_x1,*p_xf,*p_xi,*p_xr,*p_yln,*p_y2,*p_br,*p_mg,*p_h1,*p_h2;
    float *p_W2a,*p_W2b,*p_Wm,*p_CM0,*p_CM20,*p_CM1,*p_CM21;
    cudaGetSymbolAddress((void**)&p_res, g_res);
    cudaGetSymbolAddress((void**)&p_cv,  g_cv);
    cudaGetSymbolAddress((void**)&p_x1,  g_x1);
    cudaGetSymbolAddress((void**)&p_xf,  g_xf);
    cudaGetSymbolAddress((void**)&p_xi,  g_xi);
    cudaGetSymbolAddress((void**)&p_xr,  g_xr);
    cudaGetSymbolAddress((void**)&p_yln, g_yln);
    cudaGetSymbolAddress((void**)&p_y2,  g_y2);
    cudaGetSymbolAddress((void**)&p_br,  g_br);
    cudaGetSymbolAddress((void**)&p_mg,  g_mg);
    cudaGetSymbolAddress((void**)&p_h1,  g_h1);
    cudaGetSymbolAddress((void**)&p_h2,  g_h2);
    cudaGetSymbolAddress((void**)&p_W2a, g_W2a);
    cudaGetSymbolAddress((void**)&p_W2b, g_W2b);
    cudaGetSymbolAddress((void**)&p_Wm,  g_Wm);
    cudaGetSymbolAddress((void**)&p_CM0, g_CM0);
    cudaGetSymbolAddress((void**)&p_CM20,g_CM20);
    cudaGetSymbolAddress((void**)&p_CM1, g_CM1);
    cudaGetSymbolAddress((void**)&p_CM21,g_CM21);

    const int Kk[2] = {12, 24}, PD[2] = {6, 12}, NE[2] = {43, 22},
              MM[2] = {85, 43}, N2_[2] = {169, 85}, MKl[2] = {1020, 1032};
    float* CMv[2]  = {p_CM0, p_CM1};
    float* CM2v[2] = {p_CM20, p_CM21};
    float* W2v[2]  = {p_W2a, p_W2b};

    // launches 0-1: prep; 2-3: both conv GEMMs (global idx 5 = conv b1 -> ncu)
    decomp_kernel<<<dim3(NL/32, NC/32, NB), dim3(32, 32)>>>(src, p_res);
    prep_all<<<2048, 256>>>(mw, p_Wm, tw[0], p_W2a, tw[1], p_W2b,
                            p_CM0, p_CM20, p_CM1, p_CM21);

    for (int n = 0; n < 2; n++) {
        int k = Kk[n], pad = PD[n], ne = NE[n];
        int ne2 = 2*ne;
        // strided conv (even+odd interleaved), tanh
        GemmP p{};
        p.A = cw[n]; p.lda = NC*k;
        p.Bp = p_res + (size_t)n*NB*NC*NL; p.sBb = (long long)NC*NL;
        p.pad = pad; p.lhalf = LH; p.inner = NL;
        p.D = p_cv + (size_t)n*NB*NC*86; p.sDb = (long long)NC*ne2; p.ldd = ne2;
        p.bias = cb[n];
        p.M = NC; p.N = NB*ne2; p.K = NC*k; p.npos = ne2;
        if (n == 0) launch_gemm<64,128,1,12,1,1,0>(p);
        else        launch_gemm<64,64, 1,24,1,1,0>(p);
    }

    for (int n = 0; n < 2; n++) {
        int k = Kk[n], m = MM[n], N2 = N2_[n], mk = MKl[n];
        int ne2 = 2*NE[n];

        x1_kernel<<<1024, 256>>>(p_cv + (size_t)n*NB*NC*86, p_x1, m, ne2);
        { // real-DFT
            GemmP p{};
            p.A = p_x1; p.lda = m;
            p.Bp = CMv[n]; p.ldb = N2; p.sBb = 0;
            p.D = p_xf; p.sDb = 0; p.ldd = N2;
            p.M = NB*NC; p.N = N2; p.K = m; p.npos = N2;
            launch_gemm<128,64,0,1,0,0,0>(p);
        }
        { // isometric conv (valid), tanh
            GemmP p{};
            p.A = iw[n]; p.lda = NC*m;
            p.Bp = p_xf; p.sBb = (long long)NC*N2; p.inner = N2;
            p.D = p_xi; p.sDb = (long long)NC*m; p.ldd = m;
            p.bias = ib[n];
            p.M = NC; p.N = NB*m; p.K = NC*m; p.npos = m;
            if (n == 0) launch_gemm<64,128,2,85,1,1,0>(p);
            else        launch_gemm<64,64, 2,43,1,1,0>(p);
        }
        { // real-IDFT
            GemmP p{};
            p.A = p_xi; p.lda = m;
            p.Bp = CM2v[n]; p.ldb = m; p.sBb = 0;
            p.D = p_xr; p.sDb = 0; p.ldd = m;
            p.M = NB*NC; p.N = m; p.K = m; p.npos = m;
            launch_gemm<128,64,0,1,0,0,0>(p);
        }
        ln1_kernel<<<NB*m, 256>>>(p_xr, p_x1, ng, nb, p_yln, m);
        { // conv-transpose (stride==kernel), tanh, scatter store
            GemmP p{};
            p.A = W2v[n]; p.lda = NC;
            p.Bp = p_yln; p.ldb = m; p.sBb = (long long)NC*m;
            p.D = p_y2; p.sDb = (long long)NC*mk; p.kt = k; p.mklen = mk;
            p.bias = tb[n];
            p.M = NC*k; p.N = NB*m; p.K = NC; p.npos = m;
            launch_gemm<128,128,0,1,3,1,1>(p);
        }
        branch_out_kernel<<<NB*NL, 256>>>(p_y2, p_res + (size_t)n*NB*NC*NL, ng, nb, p_br, mk, n);
    }
    { // merge
        GemmP p{};
        p.A = p_br; p.lda = 2*NC;
        p.Bp = p_Wm; p.ldb = NC; p.sBb = 0;
        p.D = p_mg; p.sDb = 0; p.ldd = NC;
        p.bias = mb;
        p.M = NB*NL; p.N = NC; p.K = 2*NC; p.npos = NC;
        launch_gemm<128,128,0,1,2,0,0>(p);
    }
    { // FFN layer 1 (relu)
        GemmP p{};
        p.A = p_mg; p.lda = NC;
        p.Bp = fw1; p.ldb = 4*NC; p.sBb = 0;
        p.D = p_h1; p.sDb = 0; p.ldd = 4*NC;
        p.bias = fb1;
        p.M = NB*NL; p.N = 4*NC; p.K = NC; p.npos = 4*NC;
        launch_gemm<128,128,0,1,2,2,0>(p);
    }
    { // FFN layer 2
        GemmP p{};
        p.A = p_h1; p.lda = 4*NC;
        p.Bp = fw2; p.ldb = NC; p.sBb = 0;
        p.D = p_h2; p.sDb = 0; p.ldd = NC;
        p.bias = fb2;
        p.M = NB*NL; p.N = NC; p.K = 4*NC; p.npos = NC;
        launch_gemm<128,128,0,1,2,0,0>(p);
    }
    final_ln_kernel<<<NB*NL, 256>>>(p_mg, p_h2, fng, fnb, out);
}

// round 7
// speedup vs baseline: 2.9244x; 1.3158x over previous
#include <cuda_runtime.h>
#include <math.h>
#include <stdint.h>

#define NB 32
#define NL 1024
#define NC 512
#define LH 512   // L/2

// ---------------- scratch (device globals; no allocations) ----------------
__device__ float g_res[(size_t)2*NB*NC*NL];     // [2][B][C][L]
__device__ float g_cv [(size_t)2*NB*NC*86];     // conv out interleaved, per branch
__device__ float g_x1 [(size_t)NB*NC*85];       // [B][C][m]
__device__ float g_xf [(size_t)NB*NC*169];      // [B][C][2m-1]
__device__ float g_xi [(size_t)NB*NC*85];
__device__ float g_xr [(size_t)NB*NC*85];
__device__ float g_yln[(size_t)NB*NC*85];
__device__ float g_y2 [(size_t)NB*NC*1032];     // [B][C][m*k]
__device__ float g_br [(size_t)NB*NL*2*NC];     // [B*L][2*C]
__device__ float g_mg [(size_t)NB*NL*NC];
__device__ float g_h1 [(size_t)NB*NL*4*NC];
__device__ float g_h2 [(size_t)NB*NL*NC];
__device__ float g_W2a[(size_t)NC*12*NC];
__device__ float g_W2b[(size_t)NC*24*NC];
__device__ float g_Wm [(size_t)2*NC*NC];
__device__ float g_CM0 [85*169];
__device__ float g_CM20[85*85];
__device__ float g_CM1 [43*85];
__device__ float g_CM21[43*43];
__device__ float g_part[(size_t)12*1024*1024]; // split-K partials workspace

// ---------------- series decomp ----------------
__global__ void decomp_kernel(const float* __restrict__ src, float* __restrict__ res) {
    __shared__ float s[64][33];
    int b = blockIdx.z;
    int c0 = blockIdx.y * 32;
    int l0 = blockIdx.x * 32;
    int tx = threadIdx.x, ty = threadIdx.y;
    for (int r = ty; r < 64; r += 32) {
        int l = l0 - 16 + r;
        l = l < 0 ? 0 : (l > NL - 1 ? NL - 1 : l);
        s[r][tx] = src[((size_t)b*NL + l)*NC + c0 + tx];
    }
    __syncthreads();
    int base = tx + 16;
    float s17 = 0.f;
    #pragma unroll
    for (int j = -8; j <= 8; j++) s17 += s[base + j][ty];
    float s33 = s17;
    #pragma unroll
    for (int j = 9; j <= 16; j++) s33 += s[base - j][ty] + s[base + j][ty];
    float v = s[base][ty];
    size_t o = ((size_t)(b*NC + c0 + ty))*NL + l0 + tx;
    res[o] = v - s17 / 17.0f;
    res[(size_t)NB*NC*NL + o] = v - s33 / 33.0f;
}

// ---------------- fused prep ----------------
__global__ void prep_all(const float* __restrict__ mwt, float* __restrict__ Wm,
                         const float* __restrict__ tw0, float* __restrict__ W2a,
                         const float* __restrict__ tw1, float* __restrict__ W2b,
                         float* __restrict__ CM0, float* __restrict__ CM20,
                         float* __restrict__ CM1, float* __restrict__ CM21) {
    const double TWO_PI = 6.283185307179586476925286766559;
    const int tM = NC*NC*2;
    const int tA = NC*NC*12, tB = NC*NC*24;
    const int c0 = 85*169, c1 = 85*85, c2 = 43*85, c3 = 43*43;
    int total = tM + tA + tB + c0 + c1 + c2 + c3;
    for (int idx = blockIdx.x*blockDim.x + threadIdx.x; idx < total; idx += gridDim.x*blockDim.x) {
        int i = idx;
        if (i < tM) {
            int o = i / (NC*2);
            int rem = i - o*NC*2;
            int c = rem >> 1, n = rem & 1;
            Wm[((size_t)n*NC + c)*NC + o] = mwt[i];
            continue;
        }
        i -= tM;
        if (i < tA) {
            int cin = i / (NC*12);
            int r   = i - cin*(NC*12);
            W2a[(size_t)r*NC + cin] = tw0[i];
            continue;
        }
        i -= tA;
        if (i < tB) {
            int cin = i / (NC*24);
            int r   = i - cin*(NC*24);
            W2b[(size_t)r*NC + cin] = tw1[i];
            continue;
        }
        i -= tB;
        if (i < c0) {
            int t = i / 169, f = i - t*169;
            CM0[i] = (float)cos(TWO_PI * (double)((long long)f*(t + 84)) / 169.0);
            continue;
        }
        i -= c0;
        if (i < c1) {
            int f = i / 85, t = i - f*85;
            CM20[i] = (float)(cos(TWO_PI * (double)((long long)f*t) / 85.0) / 85.0);
            continue;
        }
        i -= c1;
        if (i < c2) {
            int t = i / 85, f = i - t*85;
            CM1[i] = (float)cos(TWO_PI * (double)((long long)f*(t + 42)) / 85.0);
            continue;
        }
        i -= c2;
        {
            int f = i / 43, t = i - f*43;
            CM21[i] = (float)(cos(TWO_PI * (double)((long long)f*t) / 43.0) / 43.0);
        }
    }
}

// ---------------- x1: exp-gated interleave, drop last ----------------
__global__ void x1_kernel(const float* __restrict__ cv, float* __restrict__ x1, int m, int ne2) {
    size_t total = (size_t)NB*NC*m;
    for (size_t idx = (size_t)blockIdx.x*blockDim.x + threadIdx.x; idx < total;
         idx += (size_t)gridDim.x*blockDim.x) {
        int t = (int)(idx % m);
        size_t bc = idx / m;
        const float* c2 = cv + bc*ne2;
        x1[idx] = c2[t ^ 1] * expf(c2[t]);
    }
}

// ---------------- GEMM params ----------------
struct GemmP {
    const float* A; int lda;
    const float* Bp; int ldb; long long sBb;
    float* D; long long sDb; int ldd;
    const float* bias;
    int M, N, K;
    int npos;
    int pad, lhalf, inner;
    int kt, mklen;
    float* part;                    // split-K partials (SPLITK>1)
};

__device__ __forceinline__ uint32_t f2tf32(float v) {
    uint32_t u;
    asm("cvt.rna.tf32.f32 %0, %1;" : "=r"(u) : "f"(v));
    return u;
}
__device__ __forceinline__ void mma_tf32(float c[4], const uint32_t a[4], const uint32_t b[2]) {
    asm("mma.sync.aligned.m16n8k8.row.col.f32.tf32.tf32.f32 "
        "{%0,%1,%2,%3},{%4,%5,%6,%7},{%8,%9},{%0,%1,%2,%3};"
        : "+f"(c[0]), "+f"(c[1]), "+f"(c[2]), "+f"(c[3])
        : "r"(a[0]), "r"(a[1]), "r"(a[2]), "r"(a[3]), "r"(b[0]), "r"(b[1]));
}

template<int BMODE, int KK>
__device__ __forceinline__ float ldB(const GemmP& p, const float* bbase, int sb, int gk) {
    if (gk >= p.K) return 0.f;
    if (BMODE == 0) return bbase[(long long)gk * p.ldb];
    int cin = gk / KK, t = gk - cin*KK;
    if (BMODE == 1) {
        int s = sb + t;
        return (s >= 0 && s < p.lhalf) ? bbase[(long long)cin*p.inner + 2*s] : 0.f;
    }
    return bbase[(long long)cin*p.inner + t];
}

// tf32 mma.sync GEMM, fragment-major smem, double-buffered, optional split-K.
// BMODE: 0 dense, 1 conv-im2col(even/odd), 2 iso-im2col   (KK: conv kernel size)
// BIASM: 0 none, 1 per-row, 2 per-col(q), 3 bias[row/kt]
// ACT:   0 none, 1 tanh, 2 relu
// SMODE: 0 normal, 1 transconv scatter
// SPLITK>1: raw partials to p.part[z][row][n]; bias/act applied by reduce kernel.
// Requires: M % BM == 0.
template<int BM, int BN, int BMODE, int KK, int BIASM, int ACT, int SMODE, int SPLITK>
__global__ void __launch_bounds__(256)
gemm_k(GemmP p) {
    constexpr int BK = 32;
    constexpr int WR = BM/32;
    constexpr int WC = 8/WR;
    constexpr int WN = BN/WC;
    constexpr int NF = WN/8;
    constexpr int AG = BM/32;
    constexpr int BR = BN/32;
    constexpr int ASZ = BM*BK, BSZ = BK*BN;
    extern __shared__ float dyn[];
    float* As = dyn;
    float* Bs = dyn + 2*ASZ;

    const int tid = threadIdx.x, lane = tid & 31, warp = tid >> 5;
    const int wr = warp % WR, wc = warp / WR;
    const int m0 = blockIdx.y * BM, n0 = blockIdx.x * BN;

    int kbeg = 0, kend = p.K;
    if (SPLITK > 1) {
        int kc = ((p.K + SPLITK*BK - 1) / (SPLITK*BK)) * BK;
        kbeg = blockIdx.z * kc;
        kend = min(kbeg + kc, p.K);
    }

    // ---- hoisted fill bases ----
    const int am_ = tid >> 3, ak_ = (tid & 7) * 4;
    const float* arow[AG];
    #pragma unroll
    for (int g = 0; g < AG; g++)
        arow[g] = p.A + (long long)(m0 + am_ + 32*g) * p.lda;
    const int bn_ = tid & 31, bk_ = (tid >> 5) * 4;
    const float* bbase_r[BR];
    int sb_r[BR];
    bool nv_r[BR];
    #pragma unroll
    for (int rp = 0; rp < BR; rp++) {
        int gn = n0 + bn_ + 32*rp;
        nv_r[rp] = gn < p.N;
        int g = nv_r[rp] ? gn : 0;
        int b = 0, q = g;
        if (!(BMODE == 0 && p.sBb == 0)) { b = g / p.npos; q = g - b*p.npos; }
        int sb = 0;
        const float* bb;
        if (BMODE == 0) bb = p.Bp + b*p.sBb + q;
        else if (BMODE == 1) { int o = q >> 1, pb = q & 1; sb = o*KK - p.pad; bb = p.Bp + b*p.sBb + pb; }
        else bb = p.Bp + b*p.sBb + q;
        bbase_r[rp] = bb;
        sb_r[rp] = sb;
    }

    // ---- base-only smem store indices ----
    int aidx[AG];
    #pragma unroll
    for (int g = 0; g < AG; g++) {
        int m = am_ + 32*g;
        int wr_ = m >> 5, mi = (m & 31) >> 4, mr = m & 15;
        int kc = ak_ >> 3, kin = ak_ & 7;
        aidx[g] = (((kc*WR + wr_)*2 + mi)*32 + (mr & 7)*4 + (kin & 3))*4
                  + (mr >> 3) + 2*(kin >> 2);
    }
    int bidx[BR];
    #pragma unroll
    for (int rp = 0; rp < BR; rp++) {
        int n = bn_ + 32*rp;
        int kc = bk_ >> 3, kin = bk_ & 7;
        bidx[rp] = ((kc*(BN/8) + (n >> 3))*32 + (n & 7)*4 + (kin & 3))*2 + (kin >> 2);
    }

    float acc[2][NF][4];
    #pragma unroll
    for (int mi = 0; mi < 2; mi++)
        #pragma unroll
        for (int ni = 0; ni < NF; ni++)
            #pragma unroll
            for (int e = 0; e < 4; e++) acc[mi][ni][e] = 0.f;

    float ra[AG][4], rb[BR][4];
    #pragma unroll
    for (int g = 0; g < AG; g++)
        #pragma unroll
        for (int j = 0; j < 4; j++) {
            int gk = kbeg + ak_ + j;
            ra[g][j] = (gk < p.K) ? arow[g][gk] : 0.f;
        }
    #pragma unroll
    for (int rp = 0; rp < BR; rp++)
        #pragma unroll
        for (int j = 0; j < 4; j++)
            rb[rp][j] = nv_r[rp] ? ldB<BMODE, KK>(p, bbase_r[rp], sb_r[rp], kbeg + bk_ + j) : 0.f;
    #pragma unroll
    for (int g = 0; g < AG; g++)
        #pragma unroll
        for (int j = 0; j < 4; j++)
            As[aidx[g] + 4*j] = __uint_as_float(f2tf32(ra[g][j]));
    #pragma unroll
    for (int rp = 0; rp < BR; rp++)
        #pragma unroll
        for (int j = 0; j < 4; j++)
            Bs[bidx[rp] + 2*j] = __uint_as_float(f2tf32(rb[rp][j]));
    __syncthreads();

    int buf = 0;
    for (int k0 = kbeg; k0 < kend; k0 += BK) {
        int kn = k0 + BK;
        bool more = kn < kend;
        if (more) {
            #pragma unroll
            for (int g = 0; g < AG; g++)
                #pragma unroll
                for (int j = 0; j < 4; j++) {
                    int gk = kn + ak_ + j;
                    ra[g][j] = (gk < p.K) ? arow[g][gk] : 0.f;
                }
            #pragma unroll
            for (int rp = 0; rp < BR; rp++)
                #pragma unroll
                for (int j = 0; j < 4; j++)
                    rb[rp][j] = nv_r[rp] ? ldB<BMODE, KK>(p, bbase_r[rp], sb_r[rp], kn + bk_ + j) : 0.f;
        }
        const float* Ac = As + buf*ASZ;
        const float* Bc = Bs + buf*BSZ;
        #pragma unroll
        for (int kc = 0; kc < 4; kc++) {
            uint32_t af[2][4];
            #pragma unroll
            for (int mi = 0; mi < 2; mi++) {
                const float4 av = *(const float4*)&Ac[(((kc*WR + wr)*2 + mi)*32 + lane)*4];
                af[mi][0] = __float_as_uint(av.x);
                af[mi][1] = __float_as_uint(av.y);
                af[mi][2] = __float_as_uint(av.z);
                af[mi][3] = __float_as_uint(av.w);
            }
            uint32_t bf[NF][2];
            #pragma unroll
            for (int ni = 0; ni < NF; ni++) {
                const float2 bv = *(const float2*)&Bc[((kc*(BN/8) + wc*(WN/8) + ni)*32 + lane)*2];
                bf[ni][0] = __float_as_uint(bv.x);
                bf[ni][1] = __float_as_uint(bv.y);
            }
            #pragma unroll
            for (int mi = 0; mi < 2; mi++)
                #pragma unroll
                for (int ni = 0; ni < NF; ni++)
                    mma_tf32(acc[mi][ni], af[mi], bf[ni]);
        }
        if (more) {
            float* An = As + (buf^1)*ASZ;
            float* Bn = Bs + (buf^1)*BSZ;
            #pragma unroll
            for (int g = 0; g < AG; g++)
                #pragma unroll
                for (int j = 0; j < 4; j++)
                    An[aidx[g] + 4*j] = __uint_as_float(f2tf32(ra[g][j]));
            #pragma unroll
            for (int rp = 0; rp < BR; rp++)
                #pragma unroll
                for (int j = 0; j < 4; j++)
                    Bn[bidx[rp] + 2*j] = __uint_as_float(f2tf32(rb[rp][j]));
        }
        __syncthreads();
        buf ^= 1;
    }

    // ---- epilogue ----
    if (SPLITK > 1) {
        float* pd = p.part + (size_t)blockIdx.z * ((size_t)p.M * p.N);
        #pragma unroll
        for (int mi = 0; mi < 2; mi++)
            #pragma unroll
            for (int half = 0; half < 2; half++) {
                int row = m0 + wr*32 + mi*16 + (lane >> 2) + half*8;
                #pragma unroll
                for (int ni = 0; ni < NF; ni++)
                    #pragma unroll
                    for (int e = 0; e < 2; e++) {
                        int gn = n0 + wc*WN + ni*8 + (lane & 3)*2 + e;
                        if (gn < p.N)
                            pd[(size_t)row*p.N + gn] = acc[mi][ni][half*2 + e];
                    }
            }
        return;
    }
    #pragma unroll
    for (int mi = 0; mi < 2; mi++) {
        #pragma unroll
        for (int half = 0; half < 2; half++) {
            int row = m0 + wr*32 + mi*16 + (lane >> 2) + half*8;
            float brow = 0.f;
            if (BIASM == 1) brow = p.bias[row];
            else if (BIASM == 3) brow = p.bias[row / p.kt];
            int cout = 0, jj = 0;
            if (SMODE == 1) { cout = row / p.kt; jj = row - cout*p.kt; }
            #pragma unroll
            for (int ni = 0; ni < NF; ni++) {
                #pragma unroll
                for (int e = 0; e < 2; e++) {
                    int gn = n0 + wc*WN + ni*8 + (lane & 3)*2 + e;
                    if (gn >= p.N) continue;
                    int b, q;
                    if (SMODE == 0 && p.sDb == 0) { b = 0; q = gn; }
                    else { b = gn / p.npos; q = gn - b*p.npos; }
                    float v = acc[mi][ni][half*2 + e] + brow;
                    if (BIASM == 2) v += p.bias[q];
                    if (ACT == 1) v = tanhf(v);
                    else if (ACT == 2) v = fmaxf(v, 0.f);
                    long long addr;
                    if (SMODE == 0) addr = b*p.sDb + (long long)row*p.ldd + q;
                    else addr = b*p.sDb + (long long)cout*p.mklen + (long long)q*p.kt + jj;
                    p.D[addr] = v;
                }
            }
        }
    }
}

// ---------------- split-K reduce + bias + tanh + batched store ----------------
__global__ void reduce_ep_k(const float* __restrict__ part, float* __restrict__ D,
                            const float* __restrict__ bias,
                            int S, int M, int N, long long sDb, int ldd, int npos) {
    int idx = blockIdx.x*blockDim.x + threadIdx.x;
    if (idx >= M*N) return;
    int row = idx / N, gn = idx - row*N;
    size_t st = (size_t)M*N;
    float v = 0.f;
    for (int z = 0; z < S; z++) v += part[(size_t)z*st + idx];
    v = tanhf(v + bias[row]);
    int b = gn / npos, q = gn - b*npos;
    D[b*sDb + (long long)row*ldd + q] = v;
}

// ---------------- block reduce + layer norms ----------
__device__ __forceinline__ float blk_sum(float v) {
    __shared__ float sb[8];
    #pragma unroll
    for (int o = 16; o; o >>= 1) v += __shfl_xor_sync(0xffffffffu, v, o);
    if ((threadIdx.x & 31) == 0) sb[threadIdx.x >> 5] = v;
    __syncthreads();
    float t = 0.f;
    #pragma unroll
    for (int i = 0; i < 8; i++) t += sb[i];
    __syncthreads();
    return t;
}

__global__ void ln1_kernel(const float* __restrict__ xr, const float* __restrict__ x1,
                           const float* __restrict__ g, const float* __restrict__ bt,
                           float* __restrict__ out, int m) {
    int row = blockIdx.x;
    int b = row / m, t = row - b*m;
    int tid = threadIdx.x;
    size_t base = (size_t)b*NC*m + t;
    float v0 = xr[base + (size_t)tid*m]       + x1[base + (size_t)tid*m];
    float v1 = xr[base + (size_t)(tid+256)*m] + x1[base + (size_t)(tid+256)*m];
    float mu = blk_sum(v0 + v1) * (1.f/NC);
    float d0 = v0 - mu, d1 = v1 - mu;
    float var = blk_sum(d0*d0 + d1*d1) * (1.f/NC);
    float inv = rsqrtf(var + 1e-5f);
    out[base + (size_t)tid*m]       = d0*inv*g[tid]     + bt[tid];
    out[base + (size_t)(tid+256)*m] = d1*inv*g[tid+256] + bt[tid+256];
}

__global__ void branch_out_kernel(const float* __restrict__ y2, const float* __restrict__ resn,
                                  const float* __restrict__ g, const float* __restrict__ bt,
                                  float* __restrict__ br, int mk, int nbr) {
    int row = blockIdx.x;
    int b = row >> 10, l = row & 1023;
    int li = (l * mk) >> 10;
    int tid = threadIdx.x;
    size_t yb = (size_t)b*NC*mk + li;
    size_t rb = (size_t)b*NC*NL + l;
    float v0 = y2[yb + (size_t)tid*mk]       + resn[rb + (size_t)tid*NL];
    float v1 = y2[yb + (size_t)(tid+256)*mk] + resn[rb + (size_t)(tid+256)*NL];
    float mu = blk_sum(v0 + v1) * (1.f/NC);
    float d0 = v0 - mu, d1 = v1 - mu;
    float var = blk_sum(d0*d0 + d1*d1) * (1.f/NC);
    float inv = rsqrtf(var + 1e-5f);
    float* o = br + (size_t)row*(2*NC) + nbr*NC;
    o[tid]     = d0*inv*g[tid]     + bt[tid];
    o[tid+256] = d1*inv*g[tid+256] + bt[tid+256];
}

__global__ void final_ln_kernel(const float* __restrict__ mg, const float* __restrict__ h2,
                                const float* __restrict__ g, const float* __restrict__ bt,
                                float* __restrict__ out) {
    int row = blockIdx.x;
    int tid = threadIdx.x;
    size_t base = (size_t)row*NC;
    float v0 = mg[base + tid]       + h2[base + tid];
    float v1 = mg[base + tid + 256] + h2[base + tid + 256];
    float mu = blk_sum(v0 + v1) * (1.f/NC);
    float d0 = v0 - mu, d1 = v1 - mu;
    float var = blk_sum(d0*d0 + d1*d1) * (1.f/NC);
    float inv = rsqrtf(var + 1e-5f);
    out[base + tid]       = d0*inv*g[tid]     + bt[tid];
    out[base + tid + 256] = d1*inv*g[tid+256] + bt[tid+256];
}

template<int BM, int BN, int SPLITK>
static inline dim3 gg(int M, int N) { return dim3((N + BN - 1)/BN, M/BM, SPLITK); }

template<int BM, int BN, int BMODE, int KK, int BIASM, int ACT, int SMODE, int SPLITK = 1>
static void launch_gemm(const GemmP& p) {
    constexpr int SMEM = 2*(BM*32 + 32*BN)*4;
    if (SMEM > 48*1024)
        cudaFuncSetAttribute((const void*)gemm_k<BM,BN,BMODE,KK,BIASM,ACT,SMODE,SPLITK>,
                             cudaFuncAttributeMaxDynamicSharedMemorySize, SMEM);
    gemm_k<BM,BN,BMODE,KK,BIASM,ACT,SMODE,SPLITK><<<gg<BM,BN,SPLITK>(p.M, p.N), 256, SMEM>>>(p);
}

extern "C" void kernel_launch(void* const* d_in, const int* in_sizes, int n_in,
                              void* d_out, int out_size) {
    (void)in_sizes; (void)n_in; (void)out_size;
    const float* src   = (const float*)d_in[0];
    const float* cw[2] = {(const float*)d_in[1],  (const float*)d_in[7]};
    const float* cb[2] = {(const float*)d_in[2],  (const float*)d_in[8]};
    const float* iw[2] = {(const float*)d_in[3],  (const float*)d_in[9]};
    const float* ib[2] = {(const float*)d_in[4],  (const float*)d_in[10]};
    const float* tw[2] = {(const float*)d_in[5],  (const float*)d_in[11]};
    const float* tb[2] = {(const float*)d_in[6],  (const float*)d_in[12]};
    const float* mw  = (const float*)d_in[13];
    const float* mb  = (const float*)d_in[14];
    const float* ng  = (const float*)d_in[15];
    const float* nb  = (const float*)d_in[16];
    const float* fw1 = (const float*)d_in[17];
    const float* fb1 = (const float*)d_in[18];
    const float* fw2 = (const float*)d_in[19];
    const float* fb2 = (const float*)d_in[20];
    const float* fng = (const float*)d_in[21];
    const float* fnb = (const float*)d_in[22];
    float* out = (float*)d_out;

    float *p_res,*p_cv,*p_x1,*p_xf,*p_xi,*p_xr,*p_yln,*p_y2,*p_br,*p_mg,*p_h1,*p_h2;
    float *p_W2a,*p_W2b,*p_Wm,*p_CM0,*p_CM20,*p_CM1,*p_CM21,*p_part;
    cudaGetSymbolAddress((void**)&p_res, g_res);
    cudaGetSymbolAddress((void**)&p_cv,  g_cv);
    cudaGetSymbolAddress((void**)&p_x1,  g_x1);
    cudaGetSymbolAddress((void**)&p_xf,  g_xf);
    cudaGetSymbolAddress((void**)&p_xi,  g_xi);
    cudaGetSymbolAddress((void**)&p_xr,  g_xr);
    cudaGetSymbolAddress((void**)&p_yln, g_yln);
    cudaGetSymbolAddress((void**)&p_y2,  g_y2);
    cudaGetSymbolAddress((void**)&p_br,  g_br);
    cudaGetSymbolAddress((void**)&p_mg,  g_mg);
    cudaGetSymbolAddress((void**)&p_h1,  g_h1);
    cudaGetSymbolAddress((void**)&p_h2,  g_h2);
    cudaGetSymbolAddress((void**)&p_W2a, g_W2a);
    cudaGetSymbolAddress((void**)&p_W2b, g_W2b);
    cudaGetSymbolAddress((void**)&p_Wm,  g_Wm);
    cudaGetSymbolAddress((void**)&p_CM0, g_CM0);
    cudaGetSymbolAddress((void**)&p_CM20,g_CM20);
    cudaGetSymbolAddress((void**)&p_CM1, g_CM1);
    cudaGetSymbolAddress((void**)&p_CM21,g_CM21);
    cudaGetSymbolAddress((void**)&p_part,g_part);

    const int Kk[2] = {12, 24}, PD[2] = {6, 12}, NE[2] = {43, 22},
              MM[2] = {85, 43}, N2_[2] = {169, 85}, MKl[2] = {1020, 1032};
    float* CMv[2]  = {p_CM0, p_CM1};
    float* CM2v[2] = {p_CM20, p_CM21};
    float* W2v[2]  = {p_W2a, p_W2b};
    float* cpart[2] = {p_part, p_part + (size_t)6*1024*1024};

    // launches: 0 decomp, 1 prep, 2 conv-b0 gemm, 3 conv-b1 gemm (global 5 -> ncu)
    decomp_kernel<<<dim3(NL/32, NC/32, NB), dim3(32, 32)>>>(src, p_res);
    prep_all<<<2048, 256>>>(mw, p_Wm, tw[0], p_W2a, tw[1], p_W2b,
                            p_CM0, p_CM20, p_CM1, p_CM21);

    for (int n = 0; n < 2; n++) {
        int k = Kk[n], pad = PD[n], ne = NE[n];
        int ne2 = 2*ne;
        GemmP p{};
        p.A = cw[n]; p.lda = NC*k;
        p.Bp = p_res + (size_t)n*NB*NC*NL; p.sBb = (long long)NC*NL;
        p.pad = pad; p.lhalf = LH; p.inner = NL;
        p.part = cpart[n];
        p.bias = cb[n];
        p.M = NC; p.N = NB*ne2; p.K = NC*k; p.npos = ne2;
        if (n == 0) launch_gemm<64,128,1,12,1,1,0,4>(p);
        else        launch_gemm<64,64, 1,24,1,1,0,8>(p);
    }
    for (int n = 0; n < 2; n++) {
        int ne2 = 2*NE[n];
        int Nn = NB*ne2;
        reduce_ep_k<<<(NC*Nn + 255)/256, 256>>>(cpart[n], p_cv + (size_t)n*NB*NC*86, cb[n],
                                                (n == 0) ? 4 : 8, NC, Nn,
                                                (long long)NC*ne2, ne2, ne2);
    }

    for (int n = 0; n < 2; n++) {
        int k = Kk[n], m = MM[n], N2 = N2_[n], mk = MKl[n];
        int ne2 = 2*NE[n];

        x1_kernel<<<1024, 256>>>(p_cv + (size_t)n*NB*NC*86, p_x1, m, ne2);
        { // real-DFT
            GemmP p{};
            p.A = p_x1; p.lda = m;
            p.Bp = CMv[n]; p.ldb = N2; p.sBb = 0;
            p.D = p_xf; p.sDb = 0; p.ldd = N2;
            p.M = NB*NC; p.N = N2; p.K = m; p.npos = N2;
            launch_gemm<128,64,0,1,0,0,0>(p);
        }
        { // isometric conv (valid), tanh — split-K
            GemmP p{};
            p.A = iw[n]; p.lda = NC*m;
            p.Bp = p_xf; p.sBb = (long long)NC*N2; p.inner = N2;
            p.part = p_part;
            p.bias = ib[n];
            p.M = NC; p.N = NB*m; p.K = NC*m; p.npos = m;
            if (n == 0) launch_gemm<64,128,2,85,1,1,0,8>(p);
            else        launch_gemm<64,64, 2,43,1,1,0,8>(p);
            reduce_ep_k<<<(NC*NB*m + 255)/256, 256>>>(p_part, p_xi, ib[n],
                                                      8, NC, NB*m,
                                                      (long long)NC*m, m, m);
        }
        { // real-IDFT
            GemmP p{};
            p.A = p_xi; p.lda = m;
            p.Bp = CM2v[n]; p.ldb = m; p.sBb = 0;
            p.D = p_xr; p.sDb = 0; p.ldd = m;
            p.M = NB*NC; p.N = m; p.K = m; p.npos = m;
            launch_gemm<128,64,0,1,0,0,0>(p);
        }
        ln1_kernel<<<NB*m, 256>>>(p_xr, p_x1, ng, nb, p_yln, m);
        { // conv-transpose (stride==kernel), tanh, scatter store
            GemmP p{};
            p.A = W2v[n]; p.lda = NC;
            p.Bp = p_yln; p.ldb = m; p.sBb = (long long)NC*m;
            p.D = p_y2; p.sDb = (long long)NC*mk; p.kt = k; p.mklen = mk;
            p.bias = tb[n];
            p.M = NC*k; p.N = NB*m; p.K = NC; p.npos = m;
            launch_gemm<128,128,0,1,3,1,1>(p);
        }
        branch_out_kernel<<<NB*NL, 256>>>(p_y2, p_res + (size_t)n*NB*NC*NL, ng, nb, p_br, mk, n);
    }
    { // merge
        GemmP p{};
        p.A = p_br; p.lda = 2*NC;
        p.Bp = p_Wm; p.ldb = NC; p.sBb = 0;
        p.D = p_mg; p.sDb = 0; p.ldd = NC;
        p.bias = mb;
        p.M = NB*NL; p.N = NC; p.K = 2*NC; p.npos = NC;
        launch_gemm<128,128,0,1,2,0,0>(p);
    }
    { // FFN layer 1 (relu)
        GemmP p{};
        p.A = p_mg; p.lda = NC;
        p.Bp = fw1; p.ldb = 4*NC; p.sBb = 0;
        p.D = p_h1; p.sDb = 0; p.ldd = 4*NC;
        p.bias = fb1;
        p.M = NB*NL; p.N = 4*NC; p.K = NC; p.npos = 4*NC;
        launch_gemm<128,128,0,1,2,2,0>(p);
    }
    { // FFN layer 2
        GemmP p{};
        p.A = p_h1; p.lda = 4*NC;
        p.Bp = fw2; p.ldb = NC; p.sBb = 0;
        p.D = p_h2; p.sDb = 0; p.ldd = NC;
        p.bias = fb2;
        p.M = NB*NL; p.N = NC; p.K = 4*NC; p.npos = NC;
        launch_gemm<128,128,0,1,2,0,0>(p);
    }
    final_ln_kernel<<<NB*NL, 256>>>(p_mg, p_h2, fng, fnb, out);
}